// round 8
// baseline (speedup 1.0000x reference)
#include <cuda_runtime.h>
#include <cuda_bf16.h>
#include <math_constants.h>

// Problem constants (fixed by the reference: V=1024, F=2048, P=8192)
#define V_N 1024
#define F_N 2048
#define P_N 8192
#define EPSF 1e-12f

#define FT 256                 // faces per split (staged in SMEM)
#define NSPLIT (F_N / FT)      // 8
#define TPB 128                // threads per block = points per block

// Cross-split (dist2, face) argmin scratch. Packed so that:
//   high 32 bits = float bits of dist2 (>=0 -> monotonic as uint)
//   low  32 bits = face index (ties -> lowest index wins == jnp.argmin first-match)
__device__ unsigned long long g_pack[P_N];

// ---- exact IEEE helpers (never contracted by ptxas) ----
__device__ __forceinline__ float fm(float a, float b) { return __fmul_rn(a, b); }
__device__ __forceinline__ float fa(float a, float b) { return __fadd_rn(a, b); }
__device__ __forceinline__ float fs(float a, float b) { return __fsub_rn(a, b); }
__device__ __forceinline__ float fd(float a, float b) { return __fdiv_rn(a, b); }
// dot3 with XLA reduce order: ((x0*y0 + x1*y1) + x2*y2), no fma
__device__ __forceinline__ float dot3(float x0, float x1, float x2,
                                      float y0, float y1, float y2) {
    return fa(fa(fm(x0, y0), fm(x1, y1)), fm(x2, y2));
}

__global__ void msdf_init_kernel() {
    int i = blockIdx.x * blockDim.x + threadIdx.x;
    if (i < P_N) g_pack[i] = 0xFFFFFFFFFFFFFFFFull;
}

__global__ __launch_bounds__(TPB)
void msdf_main_kernel(const float* __restrict__ verts,
                      const int*   __restrict__ faces,
                      const float* __restrict__ points) {
    // SoA triangle stage: a, b, c vertices of FT faces
    __shared__ float sax[FT], say[FT], saz[FT];
    __shared__ float sbx[FT], sby[FT], sbz[FT];
    __shared__ float scx[FT], scy[FT], scz[FT];

    const int fbase = blockIdx.y * FT;

    for (int i = threadIdx.x; i < FT; i += TPB) {
        int f  = fbase + i;
        int i0 = faces[3 * f + 0];
        int i1 = faces[3 * f + 1];
        int i2 = faces[3 * f + 2];
        sax[i] = verts[3 * i0 + 0]; say[i] = verts[3 * i0 + 1]; saz[i] = verts[3 * i0 + 2];
        sbx[i] = verts[3 * i1 + 0]; sby[i] = verts[3 * i1 + 1]; sbz[i] = verts[3 * i1 + 2];
        scx[i] = verts[3 * i2 + 0]; scy[i] = verts[3 * i2 + 1]; scz[i] = verts[3 * i2 + 2];
    }
    __syncthreads();

    const int p = blockIdx.x * TPB + threadIdx.x;
    const float px = points[3 * p + 0];
    const float py = points[3 * p + 1];
    const float pz = points[3 * p + 2];

    float best  = CUDART_INF_F;
    int   bestf = fbase;

    #pragma unroll 4
    for (int i = 0; i < FT; ++i) {
        // Broadcast loads (all lanes same face -> conflict-free)
        const float ax = sax[i], ay = say[i], az = saz[i];
        const float bx = sbx[i], by = sby[i], bz = sbz[i];
        const float cx = scx[i], cy = scy[i], cz = scz[i];

        // Ericson closest-point-on-triangle, bit-for-bit with the XLA reference:
        // plain IEEE mul/add/sub (no fma), left-assoc 3-term sums, div.rn.
        const float abx = fs(bx, ax), aby = fs(by, ay), abz = fs(bz, az);
        const float acx = fs(cx, ax), acy = fs(cy, ay), acz = fs(cz, az);

        const float apx = fs(px, ax), apy = fs(py, ay), apz = fs(pz, az);
        const float d1 = dot3(abx, aby, abz, apx, apy, apz);
        const float d2 = dot3(acx, acy, acz, apx, apy, apz);

        const float bpx = fs(px, bx), bpy = fs(py, by), bpz = fs(pz, bz);
        const float d3 = dot3(abx, aby, abz, bpx, bpy, bpz);
        const float d4 = dot3(acx, acy, acz, bpx, bpy, bpz);

        const float qx = fs(px, cx), qy = fs(py, cy), qz = fs(pz, cz);
        const float d5 = dot3(abx, aby, abz, qx, qy, qz);
        const float d6 = dot3(acx, acy, acz, qx, qy, qz);

        const float vc = fs(fm(d1, d4), fm(d3, d2));
        const float vb = fs(fm(d5, d2), fm(d1, d6));
        const float va = fs(fm(d3, d6), fm(d5, d4));

        const float nbc = fs(d4, d3);               // d4 - d3
        const float s56 = fs(d5, d6);               // d5 - d6
        const float denom = fmaxf(fa(fa(va, vb), vc), EPSF);

        // first-match region selection (A, B, AB, C, AC, BC, interior)
        const bool cA  = (d1 <= 0.0f) && (d2 <= 0.0f);
        const bool cB  = (d3 >= 0.0f) && (d4 <= d3);
        const bool cAB = (vc <= 0.0f) && (d1 >= 0.0f) && (d3 <= 0.0f);
        const bool cC  = (d6 >= 0.0f) && (d5 <= d6);
        const bool cAC = (vb <= 0.0f) && (d2 >= 0.0f) && (d6 <= 0.0f);
        const bool cBC = (va <= 0.0f) && (nbc >= 0.0f) && (s56 >= 0.0f);

        const int region = cA ? 0 : cB ? 1 : cAB ? 2 : cC ? 3 : cAC ? 4 : cBC ? 5 : 6;

        // Branch-free: exactly TWO div.rn per iteration, with operands chosen so
        // the SELECTED branch's value is bit-identical to the reference's.
        // bv division: region 2 -> t_ab, region 5 -> t_bc (then 1-t), else vb/denom
        float numv = (region == 2) ? d1  : (region == 5) ? nbc : vb;
        float denv = (region == 2) ? fmaxf(fs(d1, d3), EPSF)
                   : (region == 5) ? fmaxf(fa(nbc, s56), EPSF)
                   : denom;
        // bw division: region 4 -> t_ac, region 5 -> t_bc, else vc/denom
        float numw = (region == 4) ? d2  : (region == 5) ? nbc : vc;
        float denw = (region == 4) ? fmaxf(fs(d2, d6), EPSF)
                   : (region == 5) ? fmaxf(fa(nbc, s56), EPSF)
                   : denom;

        const float qv = fd(numv, denv);
        const float qw = fd(numw, denw);

        float bv = (region == 0 || region == 3 || region == 4) ? 0.0f
                 : (region == 1) ? 1.0f
                 : (region == 5) ? fs(1.0f, qv)
                 : qv;
        float bw = (region <= 2) ? 0.0f
                 : (region == 3) ? 1.0f
                 : qw;

        const float bu = fs(fs(1.0f, bv), bw);      // (1 - bv) - bw

        // cp = ((a*bu) + (b*bv)) + (c*bw), per component
        const float ox = fa(fa(fm(ax, bu), fm(bx, bv)), fm(cx, bw));
        const float oy = fa(fa(fm(ay, bu), fm(by, bv)), fm(cy, bw));
        const float oz = fa(fa(fm(az, bu), fm(bz, bv)), fm(cz, bw));

        // dist2 = ((dx^2 + dy^2) + dz^2)
        const float dx = fs(px, ox), dy = fs(py, oy), dz = fs(pz, oz);
        const float d2v = fa(fa(fm(dx, dx), fm(dy, dy)), fm(dz, dz));

        if (d2v < best) {   // strict < keeps earliest face on exact ties
            best  = d2v;
            bestf = fbase + i;
        }
    }

    const unsigned long long pk =
        ((unsigned long long)__float_as_uint(best) << 32) | (unsigned int)bestf;
    atomicMin(&g_pack[p], pk);
}

// Deterministic finalize: unpack dist/assoc, fixed-order sum for the loss.
__global__ __launch_bounds__(256)
void msdf_final_kernel(float* __restrict__ out) {
    __shared__ float ssum[256];
    const int tid = threadIdx.x;

    float acc = 0.0f;
    for (int p = tid; p < P_N; p += 256) {
        const unsigned long long pk = g_pack[p];
        const float d = __uint_as_float((unsigned int)(pk >> 32));
        const int idx = (int)(unsigned int)(pk & 0xFFFFFFFFull);
        out[1 + p]        = d;
        out[1 + P_N + p]  = (float)idx;
        acc += d;
    }
    ssum[tid] = acc;
    __syncthreads();
    #pragma unroll
    for (int s = 128; s > 0; s >>= 1) {
        if (tid < s) ssum[tid] += ssum[tid + s];
        __syncthreads();
    }
    if (tid == 0) out[0] = ssum[0] * (1000.0f / (float)P_N);
}

extern "C" void kernel_launch(void* const* d_in, const int* in_sizes, int n_in,
                              void* d_out, int out_size) {
    const float* verts  = (const float*)d_in[0];   // [V,3]
    const int*   faces  = (const int*)  d_in[1];   // [F,3]
    const float* points = (const float*)d_in[2];   // [P,3]
    float* out = (float*)d_out;                    // [1 + P + P] float32

    msdf_init_kernel<<<(P_N + 255) / 256, 256>>>();
    msdf_main_kernel<<<dim3(P_N / TPB, NSPLIT), TPB>>>(verts, faces, points);
    msdf_final_kernel<<<1, 256>>>(out);
}

// round 9
// speedup vs baseline: 1.0755x; 1.0755x over previous
#include <cuda_runtime.h>
#include <cuda_bf16.h>
#include <math_constants.h>

// Problem constants (fixed by the reference: V=1024, F=2048, P=8192)
#define V_N 1024
#define F_N 2048
#define P_N 8192
#define EPSF 1e-12f

#define FT 128                 // faces per split (staged in SMEM)
#define NSPLIT (F_N / FT)      // 16
#define TPB 128                // threads per block
#define PPT 2                  // points per thread (explicit ILP)
#define PPB (TPB * PPT)        // 256 points per block

// Cross-split (dist2, face) argmin scratch. Packed so that:
//   high 32 bits = float bits of dist2 (>=0 -> monotonic as uint)
//   low  32 bits = face index (ties -> lowest index wins == jnp.argmin first-match)
__device__ unsigned long long g_pack[P_N];

// ---- exact IEEE helpers (never contracted by ptxas) ----
__device__ __forceinline__ float fm(float a, float b) { return __fmul_rn(a, b); }
__device__ __forceinline__ float fa(float a, float b) { return __fadd_rn(a, b); }
__device__ __forceinline__ float fs(float a, float b) { return __fsub_rn(a, b); }
__device__ __forceinline__ float fd(float a, float b) { return __fdiv_rn(a, b); }
// dot3 with XLA reduce order: ((x0*y0 + x1*y1) + x2*y2), no fma
__device__ __forceinline__ float dot3(float x0, float x1, float x2,
                                      float y0, float y1, float y2) {
    return fa(fa(fm(x0, y0), fm(x1, y1)), fm(x2, y2));
}

__global__ void msdf_init_kernel() {
    int i = blockIdx.x * blockDim.x + threadIdx.x;
    if (i < P_N) g_pack[i] = 0xFFFFFFFFFFFFFFFFull;
}

// One point vs one triangle: bit-for-bit with the XLA reference.
__device__ __forceinline__ void point_face(
    float px, float py, float pz,
    float ax, float ay, float az,
    float bx, float by, float bz,
    float cx, float cy, float cz,
    int fidx, float& best, int& bestf)
{
    const float abx = fs(bx, ax), aby = fs(by, ay), abz = fs(bz, az);
    const float acx = fs(cx, ax), acy = fs(cy, ay), acz = fs(cz, az);

    const float apx = fs(px, ax), apy = fs(py, ay), apz = fs(pz, az);
    const float d1 = dot3(abx, aby, abz, apx, apy, apz);
    const float d2 = dot3(acx, acy, acz, apx, apy, apz);

    const float bpx = fs(px, bx), bpy = fs(py, by), bpz = fs(pz, bz);
    const float d3 = dot3(abx, aby, abz, bpx, bpy, bpz);
    const float d4 = dot3(acx, acy, acz, bpx, bpy, bpz);

    const float qx = fs(px, cx), qy = fs(py, cy), qz = fs(pz, cz);
    const float d5 = dot3(abx, aby, abz, qx, qy, qz);
    const float d6 = dot3(acx, acy, acz, qx, qy, qz);

    const float vc = fs(fm(d1, d4), fm(d3, d2));
    const float vb = fs(fm(d5, d2), fm(d1, d6));
    const float va = fs(fm(d3, d6), fm(d5, d4));

    const float nbc = fs(d4, d3);               // d4 - d3
    const float s56 = fs(d5, d6);               // d5 - d6
    const float denom = fmaxf(fa(fa(va, vb), vc), EPSF);

    // first-match region selection (A, B, AB, C, AC, BC, interior)
    const bool cA  = (d1 <= 0.0f) && (d2 <= 0.0f);
    const bool cB  = (d3 >= 0.0f) && (d4 <= d3);
    const bool cAB = (vc <= 0.0f) && (d1 >= 0.0f) && (d3 <= 0.0f);
    const bool cC  = (d6 >= 0.0f) && (d5 <= d6);
    const bool cAC = (vb <= 0.0f) && (d2 >= 0.0f) && (d6 <= 0.0f);
    const bool cBC = (va <= 0.0f) && (nbc >= 0.0f) && (s56 >= 0.0f);

    const int region = cA ? 0 : cB ? 1 : cAB ? 2 : cC ? 3 : cAC ? 4 : cBC ? 5 : 6;

    // Exactly TWO div.rn per pair, operands chosen so the SELECTED branch's
    // value is bit-identical to the reference's.
    float numv = (region == 2) ? d1  : (region == 5) ? nbc : vb;
    float denv = (region == 2) ? fmaxf(fs(d1, d3), EPSF)
               : (region == 5) ? fmaxf(fa(nbc, s56), EPSF)
               : denom;
    float numw = (region == 4) ? d2  : (region == 5) ? nbc : vc;
    float denw = (region == 4) ? fmaxf(fs(d2, d6), EPSF)
               : (region == 5) ? fmaxf(fa(nbc, s56), EPSF)
               : denom;

    const float qv = fd(numv, denv);
    const float qw = fd(numw, denw);

    float bv = (region == 0 || region == 3 || region == 4) ? 0.0f
             : (region == 1) ? 1.0f
             : (region == 5) ? fs(1.0f, qv)
             : qv;
    float bw = (region <= 2) ? 0.0f
             : (region == 3) ? 1.0f
             : qw;

    const float bu = fs(fs(1.0f, bv), bw);      // (1 - bv) - bw

    // cp = ((a*bu) + (b*bv)) + (c*bw), per component
    const float ox = fa(fa(fm(ax, bu), fm(bx, bv)), fm(cx, bw));
    const float oy = fa(fa(fm(ay, bu), fm(by, bv)), fm(cy, bw));
    const float oz = fa(fa(fm(az, bu), fm(bz, bv)), fm(cz, bw));

    // dist2 = ((dx^2 + dy^2) + dz^2)
    const float dx = fs(px, ox), dy = fs(py, oy), dz = fs(pz, oz);
    const float d2v = fa(fa(fm(dx, dx), fm(dy, dy)), fm(dz, dz));

    if (d2v < best) {   // strict < keeps earliest face on exact ties
        best  = d2v;
        bestf = fidx;
    }
}

__global__ __launch_bounds__(TPB)
void msdf_main_kernel(const float* __restrict__ verts,
                      const int*   __restrict__ faces,
                      const float* __restrict__ points) {
    // float4-packed face stage: stri[i][0]=(ax,ay,az,bx) stri[i][1]=(by,bz,cx,cy)
    // stri[i][2]=(cz,-,-,-). Broadcast LDS.128, conflict-free.
    __shared__ float4 stri[FT][3];

    const int fbase = blockIdx.y * FT;
    const int tid = threadIdx.x;

    // Load this thread's two points first (overlaps with staging latency).
    const int p0 = blockIdx.x * PPB + tid;
    const int p1 = p0 + TPB;
    const float px0 = points[3 * p0 + 0];
    const float py0 = points[3 * p0 + 1];
    const float pz0 = points[3 * p0 + 2];
    const float px1 = points[3 * p1 + 0];
    const float py1 = points[3 * p1 + 1];
    const float pz1 = points[3 * p1 + 2];

    // Stage FT faces (one per thread).
    {
        const int f  = fbase + tid;
        const int i0 = faces[3 * f + 0];
        const int i1 = faces[3 * f + 1];
        const int i2 = faces[3 * f + 2];
        const float ax = verts[3 * i0 + 0], ay = verts[3 * i0 + 1], az = verts[3 * i0 + 2];
        const float bx = verts[3 * i1 + 0], by = verts[3 * i1 + 1], bz = verts[3 * i1 + 2];
        const float cx = verts[3 * i2 + 0], cy = verts[3 * i2 + 1], cz = verts[3 * i2 + 2];
        stri[tid][0] = make_float4(ax, ay, az, bx);
        stri[tid][1] = make_float4(by, bz, cx, cy);
        stri[tid][2] = make_float4(cz, 0.0f, 0.0f, 0.0f);
    }
    __syncthreads();

    float best0 = CUDART_INF_F, best1 = CUDART_INF_F;
    int   bestf0 = fbase,       bestf1 = fbase;

    #pragma unroll 2
    for (int i = 0; i < FT; ++i) {
        const float4 t0 = stri[i][0];
        const float4 t1 = stri[i][1];
        const float4 t2 = stri[i][2];
        const float ax = t0.x, ay = t0.y, az = t0.z;
        const float bx = t0.w, by = t1.x, bz = t1.y;
        const float cx = t1.z, cy = t1.w, cz = t2.x;
        const int fidx = fbase + i;

        point_face(px0, py0, pz0, ax, ay, az, bx, by, bz, cx, cy, cz,
                   fidx, best0, bestf0);
        point_face(px1, py1, pz1, ax, ay, az, bx, by, bz, cx, cy, cz,
                   fidx, best1, bestf1);
    }

    const unsigned long long pk0 =
        ((unsigned long long)__float_as_uint(best0) << 32) | (unsigned int)bestf0;
    const unsigned long long pk1 =
        ((unsigned long long)__float_as_uint(best1) << 32) | (unsigned int)bestf1;
    atomicMin(&g_pack[p0], pk0);
    atomicMin(&g_pack[p1], pk1);
}

// Deterministic finalize: unpack dist/assoc, fixed-order sum for the loss.
__global__ __launch_bounds__(256)
void msdf_final_kernel(float* __restrict__ out) {
    __shared__ float ssum[256];
    const int tid = threadIdx.x;

    float acc = 0.0f;
    for (int p = tid; p < P_N; p += 256) {
        const unsigned long long pk = g_pack[p];
        const float d = __uint_as_float((unsigned int)(pk >> 32));
        const int idx = (int)(unsigned int)(pk & 0xFFFFFFFFull);
        out[1 + p]        = d;
        out[1 + P_N + p]  = (float)idx;
        acc += d;
    }
    ssum[tid] = acc;
    __syncthreads();
    #pragma unroll
    for (int s = 128; s > 0; s >>= 1) {
        if (tid < s) ssum[tid] += ssum[tid + s];
        __syncthreads();
    }
    if (tid == 0) out[0] = ssum[0] * (1000.0f / (float)P_N);
}

extern "C" void kernel_launch(void* const* d_in, const int* in_sizes, int n_in,
                              void* d_out, int out_size) {
    const float* verts  = (const float*)d_in[0];   // [V,3]
    const int*   faces  = (const int*)  d_in[1];   // [F,3]
    const float* points = (const float*)d_in[2];   // [P,3]
    float* out = (float*)d_out;                    // [1 + P + P] float32

    msdf_init_kernel<<<(P_N + 255) / 256, 256>>>();
    msdf_main_kernel<<<dim3(P_N / PPB, NSPLIT), TPB>>>(verts, faces, points);
    msdf_final_kernel<<<1, 256>>>(out);
}

// round 10
// speedup vs baseline: 1.0784x; 1.0027x over previous
#include <cuda_runtime.h>
#include <cuda_bf16.h>
#include <math_constants.h>

// Problem constants (fixed by the reference: V=1024, F=2048, P=8192)
#define V_N 1024
#define F_N 2048
#define P_N 8192
#define EPSF 1e-12f

#define FT 128                 // faces per split (staged in SMEM)
#define NSPLIT (F_N / FT)      // 16
#define TPB 128                // threads per block
#define PPT 2                  // points per thread (explicit ILP)
#define PPB (TPB * PPT)        // 256 points per block

// Cross-split (dist2, face) argmin scratch. Packed so that:
//   high 32 bits = float bits of dist2 (>=0 -> monotonic as uint)
//   low  32 bits = face index (ties -> lowest index wins == jnp.argmin first-match)
__device__ unsigned long long g_pack[P_N];

// ---- exact IEEE helpers (never contracted by ptxas) ----
__device__ __forceinline__ float fm(float a, float b) { return __fmul_rn(a, b); }
__device__ __forceinline__ float fa(float a, float b) { return __fadd_rn(a, b); }
__device__ __forceinline__ float fs(float a, float b) { return __fsub_rn(a, b); }
__device__ __forceinline__ float fd(float a, float b) { return __fdiv_rn(a, b); }
// dot3 with XLA reduce order: ((x0*y0 + x1*y1) + x2*y2), no fma
__device__ __forceinline__ float dot3(float x0, float x1, float x2,
                                      float y0, float y1, float y2) {
    return fa(fa(fm(x0, y0), fm(x1, y1)), fm(x2, y2));
}

__global__ void msdf_init_kernel() {
    int i = blockIdx.x * blockDim.x + threadIdx.x;
    if (i < P_N) g_pack[i] = 0xFFFFFFFFFFFFFFFFull;
}

// One point vs one triangle: bit-for-bit with the XLA reference.
__device__ __forceinline__ void point_face(
    float px, float py, float pz,
    float ax, float ay, float az,
    float bx, float by, float bz,
    float cx, float cy, float cz,
    int fidx, float& best, int& bestf)
{
    const float abx = fs(bx, ax), aby = fs(by, ay), abz = fs(bz, az);
    const float acx = fs(cx, ax), acy = fs(cy, ay), acz = fs(cz, az);

    const float apx = fs(px, ax), apy = fs(py, ay), apz = fs(pz, az);
    const float d1 = dot3(abx, aby, abz, apx, apy, apz);
    const float d2 = dot3(acx, acy, acz, apx, apy, apz);

    const float bpx = fs(px, bx), bpy = fs(py, by), bpz = fs(pz, bz);
    const float d3 = dot3(abx, aby, abz, bpx, bpy, bpz);
    const float d4 = dot3(acx, acy, acz, bpx, bpy, bpz);

    const float qx = fs(px, cx), qy = fs(py, cy), qz = fs(pz, cz);
    const float d5 = dot3(abx, aby, abz, qx, qy, qz);
    const float d6 = dot3(acx, acy, acz, qx, qy, qz);

    const float vc = fs(fm(d1, d4), fm(d3, d2));
    const float vb = fs(fm(d5, d2), fm(d1, d6));
    const float va = fs(fm(d3, d6), fm(d5, d4));

    const float nbc = fs(d4, d3);               // d4 - d3
    const float s56 = fs(d5, d6);               // d5 - d6
    const float denom = fmaxf(fa(fa(va, vb), vc), EPSF);

    // first-match region selection (A, B, AB, C, AC, BC, interior)
    const bool cA  = (d1 <= 0.0f) && (d2 <= 0.0f);
    const bool cB  = (d3 >= 0.0f) && (d4 <= d3);
    const bool cAB = (vc <= 0.0f) && (d1 >= 0.0f) && (d3 <= 0.0f);
    const bool cC  = (d6 >= 0.0f) && (d5 <= d6);
    const bool cAC = (vb <= 0.0f) && (d2 >= 0.0f) && (d6 <= 0.0f);
    const bool cBC = (va <= 0.0f) && (nbc >= 0.0f) && (s56 >= 0.0f);

    const int region = cA ? 0 : cB ? 1 : cAB ? 2 : cC ? 3 : cAC ? 4 : cBC ? 5 : 6;

    // Exactly TWO div.rn per pair, operands chosen so the SELECTED branch's
    // value is bit-identical to the reference's.
    float numv = (region == 2) ? d1  : (region == 5) ? nbc : vb;
    float denv = (region == 2) ? fmaxf(fs(d1, d3), EPSF)
               : (region == 5) ? fmaxf(fa(nbc, s56), EPSF)
               : denom;
    float numw = (region == 4) ? d2  : (region == 5) ? nbc : vc;
    float denw = (region == 4) ? fmaxf(fs(d2, d6), EPSF)
               : (region == 5) ? fmaxf(fa(nbc, s56), EPSF)
               : denom;

    const float qv = fd(numv, denv);
    const float qw = fd(numw, denw);

    float bv = (region == 0 || region == 3 || region == 4) ? 0.0f
             : (region == 1) ? 1.0f
             : (region == 5) ? fs(1.0f, qv)
             : qv;
    float bw = (region <= 2) ? 0.0f
             : (region == 3) ? 1.0f
             : qw;

    const float bu = fs(fs(1.0f, bv), bw);      // (1 - bv) - bw

    // cp = ((a*bu) + (b*bv)) + (c*bw), per component
    const float ox = fa(fa(fm(ax, bu), fm(bx, bv)), fm(cx, bw));
    const float oy = fa(fa(fm(ay, bu), fm(by, bv)), fm(cy, bw));
    const float oz = fa(fa(fm(az, bu), fm(bz, bv)), fm(cz, bw));

    // dist2 = ((dx^2 + dy^2) + dz^2)
    const float dx = fs(px, ox), dy = fs(py, oy), dz = fs(pz, oz);
    const float d2v = fa(fa(fm(dx, dx), fm(dy, dy)), fm(dz, dz));

    if (d2v < best) {   // strict < keeps earliest face on exact ties
        best  = d2v;
        bestf = fidx;
    }
}

__global__ __launch_bounds__(TPB)
void msdf_main_kernel(const float* __restrict__ verts,
                      const int*   __restrict__ faces,
                      const float* __restrict__ points) {
    // float4-packed face stage: stri[i][0]=(ax,ay,az,bx) stri[i][1]=(by,bz,cx,cy)
    // stri[i][2]=(cz,-,-,-). Broadcast LDS.128, conflict-free.
    __shared__ float4 stri[FT][3];

    const int fbase = blockIdx.y * FT;
    const int tid = threadIdx.x;

    // Load this thread's two points first (overlaps with staging latency).
    const int p0 = blockIdx.x * PPB + tid;
    const int p1 = p0 + TPB;
    const float px0 = points[3 * p0 + 0];
    const float py0 = points[3 * p0 + 1];
    const float pz0 = points[3 * p0 + 2];
    const float px1 = points[3 * p1 + 0];
    const float py1 = points[3 * p1 + 1];
    const float pz1 = points[3 * p1 + 2];

    // Stage FT faces (one per thread).
    {
        const int f  = fbase + tid;
        const int i0 = faces[3 * f + 0];
        const int i1 = faces[3 * f + 1];
        const int i2 = faces[3 * f + 2];
        const float ax = verts[3 * i0 + 0], ay = verts[3 * i0 + 1], az = verts[3 * i0 + 2];
        const float bx = verts[3 * i1 + 0], by = verts[3 * i1 + 1], bz = verts[3 * i1 + 2];
        const float cx = verts[3 * i2 + 0], cy = verts[3 * i2 + 1], cz = verts[3 * i2 + 2];
        stri[tid][0] = make_float4(ax, ay, az, bx);
        stri[tid][1] = make_float4(by, bz, cx, cy);
        stri[tid][2] = make_float4(cz, 0.0f, 0.0f, 0.0f);
    }
    __syncthreads();

    float best0 = CUDART_INF_F, best1 = CUDART_INF_F;
    int   bestf0 = fbase,       bestf1 = fbase;

    #pragma unroll 2
    for (int i = 0; i < FT; ++i) {
        const float4 t0 = stri[i][0];
        const float4 t1 = stri[i][1];
        const float4 t2 = stri[i][2];
        const float ax = t0.x, ay = t0.y, az = t0.z;
        const float bx = t0.w, by = t1.x, bz = t1.y;
        const float cx = t1.z, cy = t1.w, cz = t2.x;
        const int fidx = fbase + i;

        point_face(px0, py0, pz0, ax, ay, az, bx, by, bz, cx, cy, cz,
                   fidx, best0, bestf0);
        point_face(px1, py1, pz1, ax, ay, az, bx, by, bz, cx, cy, cz,
                   fidx, best1, bestf1);
    }

    const unsigned long long pk0 =
        ((unsigned long long)__float_as_uint(best0) << 32) | (unsigned int)bestf0;
    const unsigned long long pk1 =
        ((unsigned long long)__float_as_uint(best1) << 32) | (unsigned int)bestf1;
    atomicMin(&g_pack[p0], pk0);
    atomicMin(&g_pack[p1], pk1);
}

// Deterministic finalize: unpack dist/assoc, fixed-order sum for the loss.
__global__ __launch_bounds__(256)
void msdf_final_kernel(float* __restrict__ out) {
    __shared__ float ssum[256];
    const int tid = threadIdx.x;

    float acc = 0.0f;
    for (int p = tid; p < P_N; p += 256) {
        const unsigned long long pk = g_pack[p];
        const float d = __uint_as_float((unsigned int)(pk >> 32));
        const int idx = (int)(unsigned int)(pk & 0xFFFFFFFFull);
        out[1 + p]        = d;
        out[1 + P_N + p]  = (float)idx;
        acc += d;
    }
    ssum[tid] = acc;
    __syncthreads();
    #pragma unroll
    for (int s = 128; s > 0; s >>= 1) {
        if (tid < s) ssum[tid] += ssum[tid + s];
        __syncthreads();
    }
    if (tid == 0) out[0] = ssum[0] * (1000.0f / (float)P_N);
}

extern "C" void kernel_launch(void* const* d_in, const int* in_sizes, int n_in,
                              void* d_out, int out_size) {
    const float* verts  = (const float*)d_in[0];   // [V,3]
    const int*   faces  = (const int*)  d_in[1];   // [F,3]
    const float* points = (const float*)d_in[2];   // [P,3]
    float* out = (float*)d_out;                    // [1 + P + P] float32

    msdf_init_kernel<<<(P_N + 255) / 256, 256>>>();
    msdf_main_kernel<<<dim3(P_N / PPB, NSPLIT), TPB>>>(verts, faces, points);
    msdf_final_kernel<<<1, 256>>>(out);
}

// round 11
// speedup vs baseline: 1.4136x; 1.3107x over previous
#include <cuda_runtime.h>
#include <cuda_bf16.h>
#include <math_constants.h>

// Problem constants (fixed by the reference: V=1024, F=2048, P=8192)
#define V_N 1024
#define F_N 2048
#define P_N 8192
#define EPSF 1e-12f

#define FT 64                  // faces per split (staged in SMEM)
#define NSPLIT (F_N / FT)      // 32
#define TPB 128                // threads per block
#define PPT 2                  // points per thread (explicit ILP)
#define PPB (TPB * PPT)        // 256 points per block

// Cross-split (dist2, face) argmin scratch. Packed so that:
//   high 32 bits = float bits of dist2 (>=0 -> monotonic as uint)
//   low  32 bits = face index (ties -> lowest index wins == jnp.argmin first-match)
__device__ unsigned long long g_pack[P_N];

// ---- exact IEEE helpers (never contracted by ptxas) ----
__device__ __forceinline__ float fm(float a, float b) { return __fmul_rn(a, b); }
__device__ __forceinline__ float fa(float a, float b) { return __fadd_rn(a, b); }
__device__ __forceinline__ float fs(float a, float b) { return __fsub_rn(a, b); }
__device__ __forceinline__ float fd(float a, float b) { return __fdiv_rn(a, b); }
// dot3 with XLA reduce order: ((x0*y0 + x1*y1) + x2*y2), no fma
__device__ __forceinline__ float dot3(float x0, float x1, float x2,
                                      float y0, float y1, float y2) {
    return fa(fa(fm(x0, y0), fm(x1, y1)), fm(x2, y2));
}

__global__ void msdf_init_kernel() {
    int i = blockIdx.x * blockDim.x + threadIdx.x;
    if (i < P_N) g_pack[i] = 0xFFFFFFFFFFFFFFFFull;
}

// One point vs one triangle: bit-for-bit with the XLA reference.
// ab/ac are hoisted per-face (identical subtraction, done at stage time).
__device__ __forceinline__ void point_face(
    float px, float py, float pz,
    float ax, float ay, float az,
    float bx, float by, float bz,
    float cx, float cy, float cz,
    float abx, float aby, float abz,
    float acx, float acy, float acz,
    int fidx, float& best, int& bestf)
{
    const float apx = fs(px, ax), apy = fs(py, ay), apz = fs(pz, az);
    const float d1 = dot3(abx, aby, abz, apx, apy, apz);
    const float d2 = dot3(acx, acy, acz, apx, apy, apz);

    const float bpx = fs(px, bx), bpy = fs(py, by), bpz = fs(pz, bz);
    const float d3 = dot3(abx, aby, abz, bpx, bpy, bpz);
    const float d4 = dot3(acx, acy, acz, bpx, bpy, bpz);

    const float qx = fs(px, cx), qy = fs(py, cy), qz = fs(pz, cz);
    const float d5 = dot3(abx, aby, abz, qx, qy, qz);
    const float d6 = dot3(acx, acy, acz, qx, qy, qz);

    const float vc = fs(fm(d1, d4), fm(d3, d2));
    const float vb = fs(fm(d5, d2), fm(d1, d6));
    const float va = fs(fm(d3, d6), fm(d5, d4));

    const float nbc = fs(d4, d3);               // d4 - d3
    const float s56 = fs(d5, d6);               // d5 - d6
    const float denom = fmaxf(fa(fa(va, vb), vc), EPSF);

    // first-match region selection (A, B, AB, C, AC, BC, interior)
    const bool cA  = (d1 <= 0.0f) && (d2 <= 0.0f);
    const bool cB  = (d3 >= 0.0f) && (d4 <= d3);
    const bool cAB = (vc <= 0.0f) && (d1 >= 0.0f) && (d3 <= 0.0f);
    const bool cC  = (d6 >= 0.0f) && (d5 <= d6);
    const bool cAC = (vb <= 0.0f) && (d2 >= 0.0f) && (d6 <= 0.0f);
    const bool cBC = (va <= 0.0f) && (nbc >= 0.0f) && (s56 >= 0.0f);

    const int region = cA ? 0 : cB ? 1 : cAB ? 2 : cC ? 3 : cAC ? 4 : cBC ? 5 : 6;

    // Exactly TWO div.rn per pair, operands chosen so the SELECTED branch's
    // value is bit-identical to the reference's.
    float numv = (region == 2) ? d1  : (region == 5) ? nbc : vb;
    float denv = (region == 2) ? fmaxf(fs(d1, d3), EPSF)
               : (region == 5) ? fmaxf(fa(nbc, s56), EPSF)
               : denom;
    float numw = (region == 4) ? d2  : (region == 5) ? nbc : vc;
    float denw = (region == 4) ? fmaxf(fs(d2, d6), EPSF)
               : (region == 5) ? fmaxf(fa(nbc, s56), EPSF)
               : denom;

    const float qv = fd(numv, denv);
    const float qw = fd(numw, denw);

    float bv = (region == 0 || region == 3 || region == 4) ? 0.0f
             : (region == 1) ? 1.0f
             : (region == 5) ? fs(1.0f, qv)
             : qv;
    float bw = (region <= 2) ? 0.0f
             : (region == 3) ? 1.0f
             : qw;

    const float bu = fs(fs(1.0f, bv), bw);      // (1 - bv) - bw

    // cp = ((a*bu) + (b*bv)) + (c*bw), per component
    const float ox = fa(fa(fm(ax, bu), fm(bx, bv)), fm(cx, bw));
    const float oy = fa(fa(fm(ay, bu), fm(by, bv)), fm(cy, bw));
    const float oz = fa(fa(fm(az, bu), fm(bz, bv)), fm(cz, bw));

    // dist2 = ((dx^2 + dy^2) + dz^2)
    const float dx = fs(px, ox), dy = fs(py, oy), dz = fs(pz, oz);
    const float d2v = fa(fa(fm(dx, dx), fm(dy, dy)), fm(dz, dz));

    if (d2v < best) {   // strict < keeps earliest face on exact ties
        best  = d2v;
        bestf = fidx;
    }
}

__global__ __launch_bounds__(TPB)
void msdf_main_kernel(const float* __restrict__ verts,
                      const int*   __restrict__ faces,
                      const float* __restrict__ points) {
    // float4-packed face stage, ab/ac precomputed at stage time:
    //   stri[i][0]=(ax,ay,az,bx)   stri[i][1]=(by,bz,cx,cy)
    //   stri[i][2]=(cz,abx,aby,abz) stri[i][3]=(acx,acy,acz,-)
    // Broadcast LDS.128, conflict-free.
    __shared__ float4 stri[FT][4];

    const int fbase = blockIdx.y * FT;
    const int tid = threadIdx.x;

    // Load this thread's two points first (overlaps with staging latency).
    const int p0 = blockIdx.x * PPB + tid;
    const int p1 = p0 + TPB;
    const float px0 = points[3 * p0 + 0];
    const float py0 = points[3 * p0 + 1];
    const float pz0 = points[3 * p0 + 2];
    const float px1 = points[3 * p1 + 0];
    const float py1 = points[3 * p1 + 1];
    const float pz1 = points[3 * p1 + 2];

    // Stage FT faces (threads 0..FT-1).
    if (tid < FT) {
        const int f  = fbase + tid;
        const int i0 = faces[3 * f + 0];
        const int i1 = faces[3 * f + 1];
        const int i2 = faces[3 * f + 2];
        const float ax = verts[3 * i0 + 0], ay = verts[3 * i0 + 1], az = verts[3 * i0 + 2];
        const float bx = verts[3 * i1 + 0], by = verts[3 * i1 + 1], bz = verts[3 * i1 + 2];
        const float cx = verts[3 * i2 + 0], cy = verts[3 * i2 + 1], cz = verts[3 * i2 + 2];
        stri[tid][0] = make_float4(ax, ay, az, bx);
        stri[tid][1] = make_float4(by, bz, cx, cy);
        stri[tid][2] = make_float4(cz, fs(bx, ax), fs(by, ay), fs(bz, az));
        stri[tid][3] = make_float4(fs(cx, ax), fs(cy, ay), fs(cz, az), 0.0f);
    }
    __syncthreads();

    float best0 = CUDART_INF_F, best1 = CUDART_INF_F;
    int   bestf0 = fbase,       bestf1 = fbase;

    #pragma unroll 4
    for (int i = 0; i < FT; ++i) {
        const float4 t0 = stri[i][0];
        const float4 t1 = stri[i][1];
        const float4 t2 = stri[i][2];
        const float4 t3 = stri[i][3];
        const float ax = t0.x, ay = t0.y, az = t0.z;
        const float bx = t0.w, by = t1.x, bz = t1.y;
        const float cx = t1.z, cy = t1.w, cz = t2.x;
        const float abx = t2.y, aby = t2.z, abz = t2.w;
        const float acx = t3.x, acy = t3.y, acz = t3.z;
        const int fidx = fbase + i;

        point_face(px0, py0, pz0, ax, ay, az, bx, by, bz, cx, cy, cz,
                   abx, aby, abz, acx, acy, acz, fidx, best0, bestf0);
        point_face(px1, py1, pz1, ax, ay, az, bx, by, bz, cx, cy, cz,
                   abx, aby, abz, acx, acy, acz, fidx, best1, bestf1);
    }

    const unsigned long long pk0 =
        ((unsigned long long)__float_as_uint(best0) << 32) | (unsigned int)bestf0;
    const unsigned long long pk1 =
        ((unsigned long long)__float_as_uint(best1) << 32) | (unsigned int)bestf1;
    atomicMin(&g_pack[p0], pk0);
    atomicMin(&g_pack[p1], pk1);
}

// Deterministic finalize: unpack dist/assoc, fixed-order sum for the loss.
__global__ __launch_bounds__(256)
void msdf_final_kernel(float* __restrict__ out) {
    __shared__ float ssum[256];
    const int tid = threadIdx.x;

    float acc = 0.0f;
    for (int p = tid; p < P_N; p += 256) {
        const unsigned long long pk = g_pack[p];
        const float d = __uint_as_float((unsigned int)(pk >> 32));
        const int idx = (int)(unsigned int)(pk & 0xFFFFFFFFull);
        out[1 + p]        = d;
        out[1 + P_N + p]  = (float)idx;
        acc += d;
    }
    ssum[tid] = acc;
    __syncthreads();
    #pragma unroll
    for (int s = 128; s > 0; s >>= 1) {
        if (tid < s) ssum[tid] += ssum[tid + s];
        __syncthreads();
    }
    if (tid == 0) out[0] = ssum[0] * (1000.0f / (float)P_N);
}

extern "C" void kernel_launch(void* const* d_in, const int* in_sizes, int n_in,
                              void* d_out, int out_size) {
    const float* verts  = (const float*)d_in[0];   // [V,3]
    const int*   faces  = (const int*)  d_in[1];   // [F,3]
    const float* points = (const float*)d_in[2];   // [P,3]
    float* out = (float*)d_out;                    // [1 + P + P] float32

    msdf_init_kernel<<<(P_N + 255) / 256, 256>>>();
    msdf_main_kernel<<<dim3(P_N / PPB, NSPLIT), TPB>>>(verts, faces, points);
    msdf_final_kernel<<<1, 256>>>(out);
}

// round 12
// speedup vs baseline: 1.4308x; 1.0122x over previous
#include <cuda_runtime.h>
#include <cuda_bf16.h>
#include <math_constants.h>

// Problem constants (fixed by the reference: V=1024, F=2048, P=8192)
#define V_N 1024
#define F_N 2048
#define P_N 8192
#define EPSF 1e-12f

#define FT 64                  // faces per split (staged in SMEM)
#define NSPLIT (F_N / FT)      // 32
#define TPB 128                // threads per block
#define PPT 2                  // points per thread (explicit ILP)
#define PPB (TPB * PPT)        // 256 points per block

// Cross-split argmin scratch, stored INVERTED so that:
//   - zero-init (module load / finalize reset) == "empty" (pk = all-ones)
//   - atomicMax(~pk) == atomicMin(pk): high bits = ~dist2_bits (monotonic),
//     low bits = ~face_idx (ties -> lowest face index wins == jnp.argmin)
// Finalize resets each slot to 0 after reading, so every graph replay sees
// a freshly initialized array. No init kernel needed.
__device__ unsigned long long g_pack[P_N];   // zero-initialized

// ---- exact IEEE helpers (never contracted by ptxas) ----
__device__ __forceinline__ float fm(float a, float b) { return __fmul_rn(a, b); }
__device__ __forceinline__ float fa(float a, float b) { return __fadd_rn(a, b); }
__device__ __forceinline__ float fs(float a, float b) { return __fsub_rn(a, b); }
__device__ __forceinline__ float fd(float a, float b) { return __fdiv_rn(a, b); }
// dot3 with XLA reduce order: ((x0*y0 + x1*y1) + x2*y2), no fma
__device__ __forceinline__ float dot3(float x0, float x1, float x2,
                                      float y0, float y1, float y2) {
    return fa(fa(fm(x0, y0), fm(x1, y1)), fm(x2, y2));
}

// One point vs one triangle: bit-for-bit with the XLA reference.
// ab/ac are hoisted per-face (identical subtraction, done at stage time).
__device__ __forceinline__ void point_face(
    float px, float py, float pz,
    float ax, float ay, float az,
    float bx, float by, float bz,
    float cx, float cy, float cz,
    float abx, float aby, float abz,
    float acx, float acy, float acz,
    int fidx, float& best, int& bestf)
{
    const float apx = fs(px, ax), apy = fs(py, ay), apz = fs(pz, az);
    const float d1 = dot3(abx, aby, abz, apx, apy, apz);
    const float d2 = dot3(acx, acy, acz, apx, apy, apz);

    const float bpx = fs(px, bx), bpy = fs(py, by), bpz = fs(pz, bz);
    const float d3 = dot3(abx, aby, abz, bpx, bpy, bpz);
    const float d4 = dot3(acx, acy, acz, bpx, bpy, bpz);

    const float qx = fs(px, cx), qy = fs(py, cy), qz = fs(pz, cz);
    const float d5 = dot3(abx, aby, abz, qx, qy, qz);
    const float d6 = dot3(acx, acy, acz, qx, qy, qz);

    const float vc = fs(fm(d1, d4), fm(d3, d2));
    const float vb = fs(fm(d5, d2), fm(d1, d6));
    const float va = fs(fm(d3, d6), fm(d5, d4));

    const float nbc = fs(d4, d3);               // d4 - d3
    const float s56 = fs(d5, d6);               // d5 - d6
    const float denom = fmaxf(fa(fa(va, vb), vc), EPSF);

    // first-match region selection (A, B, AB, C, AC, BC, interior)
    const bool cA  = (d1 <= 0.0f) && (d2 <= 0.0f);
    const bool cB  = (d3 >= 0.0f) && (d4 <= d3);
    const bool cAB = (vc <= 0.0f) && (d1 >= 0.0f) && (d3 <= 0.0f);
    const bool cC  = (d6 >= 0.0f) && (d5 <= d6);
    const bool cAC = (vb <= 0.0f) && (d2 >= 0.0f) && (d6 <= 0.0f);
    const bool cBC = (va <= 0.0f) && (nbc >= 0.0f) && (s56 >= 0.0f);

    const int region = cA ? 0 : cB ? 1 : cAB ? 2 : cC ? 3 : cAC ? 4 : cBC ? 5 : 6;

    // Exactly TWO div.rn per pair, operands chosen so the SELECTED branch's
    // value is bit-identical to the reference's.
    float numv = (region == 2) ? d1  : (region == 5) ? nbc : vb;
    float denv = (region == 2) ? fmaxf(fs(d1, d3), EPSF)
               : (region == 5) ? fmaxf(fa(nbc, s56), EPSF)
               : denom;
    float numw = (region == 4) ? d2  : (region == 5) ? nbc : vc;
    float denw = (region == 4) ? fmaxf(fs(d2, d6), EPSF)
               : (region == 5) ? fmaxf(fa(nbc, s56), EPSF)
               : denom;

    const float qv = fd(numv, denv);
    const float qw = fd(numw, denw);

    float bv = (region == 0 || region == 3 || region == 4) ? 0.0f
             : (region == 1) ? 1.0f
             : (region == 5) ? fs(1.0f, qv)
             : qv;
    float bw = (region <= 2) ? 0.0f
             : (region == 3) ? 1.0f
             : qw;

    const float bu = fs(fs(1.0f, bv), bw);      // (1 - bv) - bw

    // cp = ((a*bu) + (b*bv)) + (c*bw), per component
    const float ox = fa(fa(fm(ax, bu), fm(bx, bv)), fm(cx, bw));
    const float oy = fa(fa(fm(ay, bu), fm(by, bv)), fm(cy, bw));
    const float oz = fa(fa(fm(az, bu), fm(bz, bv)), fm(cz, bw));

    // dist2 = ((dx^2 + dy^2) + dz^2)
    const float dx = fs(px, ox), dy = fs(py, oy), dz = fs(pz, oz);
    const float d2v = fa(fa(fm(dx, dx), fm(dy, dy)), fm(dz, dz));

    if (d2v < best) {   // strict < keeps earliest face on exact ties
        best  = d2v;
        bestf = fidx;
    }
}

__global__ __launch_bounds__(TPB, 4)
void msdf_main_kernel(const float* __restrict__ verts,
                      const int*   __restrict__ faces,
                      const float* __restrict__ points) {
    // float4-packed face stage, ab/ac precomputed at stage time:
    //   stri[i][0]=(ax,ay,az,bx)   stri[i][1]=(by,bz,cx,cy)
    //   stri[i][2]=(cz,abx,aby,abz) stri[i][3]=(acx,acy,acz,-)
    // Broadcast LDS.128, conflict-free.
    __shared__ float4 stri[FT][4];

    const int fbase = blockIdx.y * FT;
    const int tid = threadIdx.x;

    // Load this thread's two points first (overlaps with staging latency).
    const int p0 = blockIdx.x * PPB + tid;
    const int p1 = p0 + TPB;
    const float px0 = points[3 * p0 + 0];
    const float py0 = points[3 * p0 + 1];
    const float pz0 = points[3 * p0 + 2];
    const float px1 = points[3 * p1 + 0];
    const float py1 = points[3 * p1 + 1];
    const float pz1 = points[3 * p1 + 2];

    // Stage FT faces (threads 0..FT-1).
    if (tid < FT) {
        const int f  = fbase + tid;
        const int i0 = faces[3 * f + 0];
        const int i1 = faces[3 * f + 1];
        const int i2 = faces[3 * f + 2];
        const float ax = verts[3 * i0 + 0], ay = verts[3 * i0 + 1], az = verts[3 * i0 + 2];
        const float bx = verts[3 * i1 + 0], by = verts[3 * i1 + 1], bz = verts[3 * i1 + 2];
        const float cx = verts[3 * i2 + 0], cy = verts[3 * i2 + 1], cz = verts[3 * i2 + 2];
        stri[tid][0] = make_float4(ax, ay, az, bx);
        stri[tid][1] = make_float4(by, bz, cx, cy);
        stri[tid][2] = make_float4(cz, fs(bx, ax), fs(by, ay), fs(bz, az));
        stri[tid][3] = make_float4(fs(cx, ax), fs(cy, ay), fs(cz, az), 0.0f);
    }
    __syncthreads();

    float best0 = CUDART_INF_F, best1 = CUDART_INF_F;
    int   bestf0 = fbase,       bestf1 = fbase;

    #pragma unroll 4
    for (int i = 0; i < FT; ++i) {
        const float4 t0 = stri[i][0];
        const float4 t1 = stri[i][1];
        const float4 t2 = stri[i][2];
        const float4 t3 = stri[i][3];
        const float ax = t0.x, ay = t0.y, az = t0.z;
        const float bx = t0.w, by = t1.x, bz = t1.y;
        const float cx = t1.z, cy = t1.w, cz = t2.x;
        const float abx = t2.y, aby = t2.z, abz = t2.w;
        const float acx = t3.x, acy = t3.y, acz = t3.z;
        const int fidx = fbase + i;

        point_face(px0, py0, pz0, ax, ay, az, bx, by, bz, cx, cy, cz,
                   abx, aby, abz, acx, acy, acz, fidx, best0, bestf0);
        point_face(px1, py1, pz1, ax, ay, az, bx, by, bz, cx, cy, cz,
                   abx, aby, abz, acx, acy, acz, fidx, best1, bestf1);
    }

    // Inverted pack: max(~pk) == min(pk); ties -> lowest face index.
    const unsigned long long pk0 =
        ~(((unsigned long long)__float_as_uint(best0) << 32) | (unsigned int)bestf0);
    const unsigned long long pk1 =
        ~(((unsigned long long)__float_as_uint(best1) << 32) | (unsigned int)bestf1);
    atomicMax(&g_pack[p0], pk0);
    atomicMax(&g_pack[p1], pk1);
}

// Deterministic finalize: unpack dist/assoc, fixed-order sum for the loss,
// and RESET g_pack to 0 ("empty") so the next graph replay starts clean.
__global__ __launch_bounds__(256)
void msdf_final_kernel(float* __restrict__ out) {
    __shared__ float ssum[256];
    const int tid = threadIdx.x;

    float acc = 0.0f;
    for (int p = tid; p < P_N; p += 256) {
        const unsigned long long pk = ~g_pack[p];   // un-invert
        g_pack[p] = 0ull;                           // re-arm for next launch
        const float d = __uint_as_float((unsigned int)(pk >> 32));
        const int idx = (int)(unsigned int)(pk & 0xFFFFFFFFull);
        out[1 + p]        = d;
        out[1 + P_N + p]  = (float)idx;
        acc += d;
    }
    ssum[tid] = acc;
    __syncthreads();
    #pragma unroll
    for (int s = 128; s > 0; s >>= 1) {
        if (tid < s) ssum[tid] += ssum[tid + s];
        __syncthreads();
    }
    if (tid == 0) out[0] = ssum[0] * (1000.0f / (float)P_N);
}

extern "C" void kernel_launch(void* const* d_in, const int* in_sizes, int n_in,
                              void* d_out, int out_size) {
    const float* verts  = (const float*)d_in[0];   // [V,3]
    const int*   faces  = (const int*)  d_in[1];   // [F,3]
    const float* points = (const float*)d_in[2];   // [P,3]
    float* out = (float*)d_out;                    // [1 + P + P] float32

    msdf_main_kernel<<<dim3(P_N / PPB, NSPLIT), TPB>>>(verts, faces, points);
    msdf_final_kernel<<<1, 256>>>(out);
}

// round 13
// speedup vs baseline: 1.5056x; 1.0523x over previous
#include <cuda_runtime.h>
#include <cuda_bf16.h>
#include <math_constants.h>

// Problem constants (fixed by the reference: V=1024, F=2048, P=8192)
#define V_N 1024
#define F_N 2048
#define P_N 8192
#define EPSF 1e-12f

#define FT 64                  // faces per split (staged in SMEM)
#define NSPLIT (F_N / FT)      // 32
#define TPB 128                // threads per block
#define PPT 2                  // points per thread (explicit ILP)
#define PPB (TPB * PPT)        // 256 points per block

#define UNPACK_BLOCKS 32
#define UNPACK_TPB 256         // 32*256 = 8192 = one point per thread

// Cross-split argmin scratch, stored INVERTED so that:
//   - zero-init (module load / unpack reset) == "empty" (pk = all-ones)
//   - atomicMax(~pk) == atomicMin(pk): high bits = ~dist2_bits (monotonic),
//     low bits = ~face_idx (ties -> lowest face index wins == jnp.argmin)
// Unpack resets each slot to 0 after reading, so every graph replay sees
// a freshly initialized array. No init kernel needed.
__device__ unsigned long long g_pack[P_N];        // zero-initialized
__device__ float g_partial[UNPACK_BLOCKS];        // per-block loss partials

// ---- exact IEEE helpers (never contracted by ptxas) ----
__device__ __forceinline__ float fm(float a, float b) { return __fmul_rn(a, b); }
__device__ __forceinline__ float fa(float a, float b) { return __fadd_rn(a, b); }
__device__ __forceinline__ float fs(float a, float b) { return __fsub_rn(a, b); }
__device__ __forceinline__ float fd(float a, float b) { return __fdiv_rn(a, b); }
// dot3 with XLA reduce order: ((x0*y0 + x1*y1) + x2*y2), no fma
__device__ __forceinline__ float dot3(float x0, float x1, float x2,
                                      float y0, float y1, float y2) {
    return fa(fa(fm(x0, y0), fm(x1, y1)), fm(x2, y2));
}

// One point vs one triangle: bit-for-bit with the XLA reference.
// ab/ac are hoisted per-face (identical subtraction, done at stage time).
__device__ __forceinline__ void point_face(
    float px, float py, float pz,
    float ax, float ay, float az,
    float bx, float by, float bz,
    float cx, float cy, float cz,
    float abx, float aby, float abz,
    float acx, float acy, float acz,
    int fidx, float& best, int& bestf)
{
    const float apx = fs(px, ax), apy = fs(py, ay), apz = fs(pz, az);
    const float d1 = dot3(abx, aby, abz, apx, apy, apz);
    const float d2 = dot3(acx, acy, acz, apx, apy, apz);

    const float bpx = fs(px, bx), bpy = fs(py, by), bpz = fs(pz, bz);
    const float d3 = dot3(abx, aby, abz, bpx, bpy, bpz);
    const float d4 = dot3(acx, acy, acz, bpx, bpy, bpz);

    const float qx = fs(px, cx), qy = fs(py, cy), qz = fs(pz, cz);
    const float d5 = dot3(abx, aby, abz, qx, qy, qz);
    const float d6 = dot3(acx, acy, acz, qx, qy, qz);

    const float vc = fs(fm(d1, d4), fm(d3, d2));
    const float vb = fs(fm(d5, d2), fm(d1, d6));
    const float va = fs(fm(d3, d6), fm(d5, d4));

    const float nbc = fs(d4, d3);               // d4 - d3
    const float s56 = fs(d5, d6);               // d5 - d6
    const float denom = fmaxf(fa(fa(va, vb), vc), EPSF);

    // first-match region selection (A, B, AB, C, AC, BC, interior)
    const bool cA  = (d1 <= 0.0f) && (d2 <= 0.0f);
    const bool cB  = (d3 >= 0.0f) && (d4 <= d3);
    const bool cAB = (vc <= 0.0f) && (d1 >= 0.0f) && (d3 <= 0.0f);
    const bool cC  = (d6 >= 0.0f) && (d5 <= d6);
    const bool cAC = (vb <= 0.0f) && (d2 >= 0.0f) && (d6 <= 0.0f);
    const bool cBC = (va <= 0.0f) && (nbc >= 0.0f) && (s56 >= 0.0f);

    const int region = cA ? 0 : cB ? 1 : cAB ? 2 : cC ? 3 : cAC ? 4 : cBC ? 5 : 6;

    // Exactly TWO div.rn per pair, operands chosen so the SELECTED branch's
    // value is bit-identical to the reference's.
    float numv = (region == 2) ? d1  : (region == 5) ? nbc : vb;
    float denv = (region == 2) ? fmaxf(fs(d1, d3), EPSF)
               : (region == 5) ? fmaxf(fa(nbc, s56), EPSF)
               : denom;
    float numw = (region == 4) ? d2  : (region == 5) ? nbc : vc;
    float denw = (region == 4) ? fmaxf(fs(d2, d6), EPSF)
               : (region == 5) ? fmaxf(fa(nbc, s56), EPSF)
               : denom;

    const float qv = fd(numv, denv);
    const float qw = fd(numw, denw);

    float bv = (region == 0 || region == 3 || region == 4) ? 0.0f
             : (region == 1) ? 1.0f
             : (region == 5) ? fs(1.0f, qv)
             : qv;
    float bw = (region <= 2) ? 0.0f
             : (region == 3) ? 1.0f
             : qw;

    const float bu = fs(fs(1.0f, bv), bw);      // (1 - bv) - bw

    // cp = ((a*bu) + (b*bv)) + (c*bw), per component
    const float ox = fa(fa(fm(ax, bu), fm(bx, bv)), fm(cx, bw));
    const float oy = fa(fa(fm(ay, bu), fm(by, bv)), fm(cy, bw));
    const float oz = fa(fa(fm(az, bu), fm(bz, bv)), fm(cz, bw));

    // dist2 = ((dx^2 + dy^2) + dz^2)
    const float dx = fs(px, ox), dy = fs(py, oy), dz = fs(pz, oz);
    const float d2v = fa(fa(fm(dx, dx), fm(dy, dy)), fm(dz, dz));

    if (d2v < best) {   // strict < keeps earliest face on exact ties
        best  = d2v;
        bestf = fidx;
    }
}

__global__ __launch_bounds__(TPB, 4)
void msdf_main_kernel(const float* __restrict__ verts,
                      const int*   __restrict__ faces,
                      const float* __restrict__ points) {
    // float4-packed face stage, ab/ac precomputed at stage time:
    //   stri[i][0]=(ax,ay,az,bx)   stri[i][1]=(by,bz,cx,cy)
    //   stri[i][2]=(cz,abx,aby,abz) stri[i][3]=(acx,acy,acz,-)
    // Broadcast LDS.128, conflict-free.
    __shared__ float4 stri[FT][4];

    const int fbase = blockIdx.y * FT;
    const int tid = threadIdx.x;

    // Load this thread's two points first (overlaps with staging latency).
    const int p0 = blockIdx.x * PPB + tid;
    const int p1 = p0 + TPB;
    const float px0 = points[3 * p0 + 0];
    const float py0 = points[3 * p0 + 1];
    const float pz0 = points[3 * p0 + 2];
    const float px1 = points[3 * p1 + 0];
    const float py1 = points[3 * p1 + 1];
    const float pz1 = points[3 * p1 + 2];

    // Stage FT faces (threads 0..FT-1).
    if (tid < FT) {
        const int f  = fbase + tid;
        const int i0 = faces[3 * f + 0];
        const int i1 = faces[3 * f + 1];
        const int i2 = faces[3 * f + 2];
        const float ax = verts[3 * i0 + 0], ay = verts[3 * i0 + 1], az = verts[3 * i0 + 2];
        const float bx = verts[3 * i1 + 0], by = verts[3 * i1 + 1], bz = verts[3 * i1 + 2];
        const float cx = verts[3 * i2 + 0], cy = verts[3 * i2 + 1], cz = verts[3 * i2 + 2];
        stri[tid][0] = make_float4(ax, ay, az, bx);
        stri[tid][1] = make_float4(by, bz, cx, cy);
        stri[tid][2] = make_float4(cz, fs(bx, ax), fs(by, ay), fs(bz, az));
        stri[tid][3] = make_float4(fs(cx, ax), fs(cy, ay), fs(cz, az), 0.0f);
    }
    __syncthreads();

    float best0 = CUDART_INF_F, best1 = CUDART_INF_F;
    int   bestf0 = fbase,       bestf1 = fbase;

    #pragma unroll 4
    for (int i = 0; i < FT; ++i) {
        const float4 t0 = stri[i][0];
        const float4 t1 = stri[i][1];
        const float4 t2 = stri[i][2];
        const float4 t3 = stri[i][3];
        const float ax = t0.x, ay = t0.y, az = t0.z;
        const float bx = t0.w, by = t1.x, bz = t1.y;
        const float cx = t1.z, cy = t1.w, cz = t2.x;
        const float abx = t2.y, aby = t2.z, abz = t2.w;
        const float acx = t3.x, acy = t3.y, acz = t3.z;
        const int fidx = fbase + i;

        point_face(px0, py0, pz0, ax, ay, az, bx, by, bz, cx, cy, cz,
                   abx, aby, abz, acx, acy, acz, fidx, best0, bestf0);
        point_face(px1, py1, pz1, ax, ay, az, bx, by, bz, cx, cy, cz,
                   abx, aby, abz, acx, acy, acz, fidx, best1, bestf1);
    }

    // Inverted pack: max(~pk) == min(pk); ties -> lowest face index.
    const unsigned long long pk0 =
        ~(((unsigned long long)__float_as_uint(best0) << 32) | (unsigned int)bestf0);
    const unsigned long long pk1 =
        ~(((unsigned long long)__float_as_uint(best1) << 32) | (unsigned int)bestf1);
    atomicMax(&g_pack[p0], pk0);
    atomicMax(&g_pack[p1], pk1);
}

// Parallel unpack: 32 blocks x 256 threads, one point per thread.
// Writes dist/assoc, re-arms g_pack, and produces one deterministic
// per-block partial sum (fixed tree order).
__global__ __launch_bounds__(UNPACK_TPB)
void msdf_unpack_kernel(float* __restrict__ out) {
    __shared__ float ssum[UNPACK_TPB];
    const int tid = threadIdx.x;
    const int p   = blockIdx.x * UNPACK_TPB + tid;

    const unsigned long long pk = ~g_pack[p];   // un-invert
    g_pack[p] = 0ull;                           // re-arm for next launch
    const float d = __uint_as_float((unsigned int)(pk >> 32));
    const int idx = (int)(unsigned int)(pk & 0xFFFFFFFFull);
    out[1 + p]       = d;
    out[1 + P_N + p] = (float)idx;

    ssum[tid] = d;
    __syncthreads();
    #pragma unroll
    for (int s = UNPACK_TPB / 2; s > 0; s >>= 1) {
        if (tid < s) ssum[tid] += ssum[tid + s];
        __syncthreads();
    }
    if (tid == 0) g_partial[blockIdx.x] = ssum[0];
}

// Tiny deterministic loss: fixed ascending-order sum of the 32 partials.
__global__ void msdf_loss_kernel(float* __restrict__ out) {
    if (threadIdx.x == 0) {
        float acc = 0.0f;
        #pragma unroll
        for (int i = 0; i < UNPACK_BLOCKS; ++i) acc += g_partial[i];
        out[0] = acc * (1000.0f / (float)P_N);
    }
}

extern "C" void kernel_launch(void* const* d_in, const int* in_sizes, int n_in,
                              void* d_out, int out_size) {
    const float* verts  = (const float*)d_in[0];   // [V,3]
    const int*   faces  = (const int*)  d_in[1];   // [F,3]
    const float* points = (const float*)d_in[2];   // [P,3]
    float* out = (float*)d_out;                    // [1 + P + P] float32

    msdf_main_kernel<<<dim3(P_N / PPB, NSPLIT), TPB>>>(verts, faces, points);
    msdf_unpack_kernel<<<UNPACK_BLOCKS, UNPACK_TPB>>>(out);
    msdf_loss_kernel<<<1, 32>>>(out);
}

// round 14
// speedup vs baseline: 1.8812x; 1.2495x over previous
#include <cuda_runtime.h>
#include <cuda_bf16.h>
#include <math_constants.h>

// Problem constants (fixed by the reference: V=1024, F=2048, P=8192)
#define V_N 1024
#define F_N 2048
#define P_N 8192
#define EPSF 1e-12f

#define FT 64                  // faces per split (staged in SMEM)
#define NSPLIT (F_N / FT)      // 32
#define TPB 128                // threads per block
#define PPT 2                  // points per thread (explicit ILP)
#define PPB (TPB * PPT)        // 256 points per block

#define UNPACK_BLOCKS 32
#define UNPACK_TPB 256         // 32*256 = 8192 = one point per thread

// Cross-split argmin scratch, stored INVERTED so that:
//   - zero-init (module load / unpack reset) == "empty" (pk = all-ones)
//   - atomicMax(~pk) == atomicMin(pk): high bits = ~dist2_bits (monotonic),
//     low bits = ~face_idx (ties -> lowest face index wins == jnp.argmin)
// Unpack resets each slot to 0 after reading, so every graph replay sees
// a freshly initialized array. No init kernel needed.
__device__ unsigned long long g_pack[P_N];        // zero-initialized
__device__ float g_partial[UNPACK_BLOCKS];        // per-block loss partials

// ---- exact IEEE helpers (never contracted by ptxas) ----
__device__ __forceinline__ float fm(float a, float b) { return __fmul_rn(a, b); }
__device__ __forceinline__ float fa(float a, float b) { return __fadd_rn(a, b); }
__device__ __forceinline__ float fs(float a, float b) { return __fsub_rn(a, b); }
__device__ __forceinline__ float fd(float a, float b) { return __fdiv_rn(a, b); }
// dot3 with XLA reduce order: ((x0*y0 + x1*y1) + x2*y2), no fma
__device__ __forceinline__ float dot3(float x0, float x1, float x2,
                                      float y0, float y1, float y2) {
    return fa(fa(fm(x0, y0), fm(x1, y1)), fm(x2, y2));
}

// One point vs one triangle: bit-for-bit with the XLA reference.
// ab/ac are hoisted per-face (identical subtraction, done at stage time).
__device__ __forceinline__ void point_face(
    float px, float py, float pz,
    float ax, float ay, float az,
    float bx, float by, float bz,
    float cx, float cy, float cz,
    float abx, float aby, float abz,
    float acx, float acy, float acz,
    int fidx, float& best, int& bestf)
{
    const float apx = fs(px, ax), apy = fs(py, ay), apz = fs(pz, az);
    const float d1 = dot3(abx, aby, abz, apx, apy, apz);
    const float d2 = dot3(acx, acy, acz, apx, apy, apz);

    const float bpx = fs(px, bx), bpy = fs(py, by), bpz = fs(pz, bz);
    const float d3 = dot3(abx, aby, abz, bpx, bpy, bpz);
    const float d4 = dot3(acx, acy, acz, bpx, bpy, bpz);

    const float qx = fs(px, cx), qy = fs(py, cy), qz = fs(pz, cz);
    const float d5 = dot3(abx, aby, abz, qx, qy, qz);
    const float d6 = dot3(acx, acy, acz, qx, qy, qz);

    const float vc = fs(fm(d1, d4), fm(d3, d2));
    const float vb = fs(fm(d5, d2), fm(d1, d6));
    const float va = fs(fm(d3, d6), fm(d5, d4));

    const float nbc = fs(d4, d3);               // d4 - d3
    const float s56 = fs(d5, d6);               // d5 - d6
    const float denom = fmaxf(fa(fa(va, vb), vc), EPSF);
    const float dAB = fmaxf(fs(d1, d3), EPSF);
    const float dAC = fmaxf(fs(d2, d6), EPSF);
    const float dBC = fmaxf(fa(nbc, s56), EPSF);

    // raw region conditions (A, B, AB, C, AC, BC)
    const bool cA  = (d1 <= 0.0f) && (d2 <= 0.0f);
    const bool cB  = (d3 >= 0.0f) && (d4 <= d3);
    const bool cAB = (vc <= 0.0f) && (d1 >= 0.0f) && (d3 <= 0.0f);
    const bool cC  = (d6 >= 0.0f) && (d5 <= d6);
    const bool cAC = (vb <= 0.0f) && (d2 >= 0.0f) && (d6 <= 0.0f);
    const bool cBC = (va <= 0.0f) && (nbc >= 0.0f) && (s56 >= 0.0f);

    // exclusive first-match predicates via cumulative-OR priority chain
    const bool n0 = cA;
    const bool n1 = n0 | cB;
    const bool n2 = n1 | cAB;
    const bool n3 = n2 | cC;
    const bool n4 = n3 | cAC;
    const bool eB  = cB  && !n0;
    const bool eAB = cAB && !n1;
    const bool eC  = cC  && !n2;
    const bool eAC = cAC && !n3;
    const bool eBC = cBC && !n4;

    // Exactly TWO div.rn per pair, operands chosen so the SELECTED branch's
    // value is bit-identical to the reference's.
    const float numv = eAB ? d1  : eBC ? nbc : vb;
    const float denv = eAB ? dAB : eBC ? dBC : denom;
    const float numw = eAC ? d2  : eBC ? nbc : vc;
    const float denw = eAC ? dAC : eBC ? dBC : denom;

    const float qv = fd(numv, denv);
    const float qw = fd(numw, denw);

    // bv: A/C/AC -> 0, B -> 1, BC -> 1-t_bc, AB/interior -> qv
    float bv = eBC ? fs(1.0f, qv) : qv;
    bv = eB ? 1.0f : bv;
    bv = (cA | eC | eAC) ? 0.0f : bv;
    // bw: A/B/AB -> 0, C -> 1, AC/BC/interior -> qw
    float bw = eC ? 1.0f : qw;
    bw = (n1 | eAB) ? 0.0f : bw;   // n1|eAB == cA|eB|eAB (first-match A,B,AB)

    const float bu = fs(fs(1.0f, bv), bw);      // (1 - bv) - bw

    // cp = ((a*bu) + (b*bv)) + (c*bw), per component
    const float ox = fa(fa(fm(ax, bu), fm(bx, bv)), fm(cx, bw));
    const float oy = fa(fa(fm(ay, bu), fm(by, bv)), fm(cy, bw));
    const float oz = fa(fa(fm(az, bu), fm(bz, bv)), fm(cz, bw));

    // dist2 = ((dx^2 + dy^2) + dz^2)
    const float dx = fs(px, ox), dy = fs(py, oy), dz = fs(pz, oz);
    const float d2v = fa(fa(fm(dx, dx), fm(dy, dy)), fm(dz, dz));

    if (d2v < best) {   // strict < keeps earliest face on exact ties
        best  = d2v;
        bestf = fidx;
    }
}

__global__ __launch_bounds__(TPB, 4)
void msdf_main_kernel(const float* __restrict__ verts,
                      const int*   __restrict__ faces,
                      const float* __restrict__ points) {
    // float4-packed face stage, ab/ac precomputed at stage time:
    //   stri[i][0]=(ax,ay,az,bx)   stri[i][1]=(by,bz,cx,cy)
    //   stri[i][2]=(cz,abx,aby,abz) stri[i][3]=(acx,acy,acz,-)
    // Broadcast LDS.128, conflict-free.
    __shared__ float4 stri[FT][4];

    const int fbase = blockIdx.y * FT;
    const int tid = threadIdx.x;

    // Load this thread's two points first (overlaps with staging latency).
    const int p0 = blockIdx.x * PPB + tid;
    const int p1 = p0 + TPB;
    const float px0 = points[3 * p0 + 0];
    const float py0 = points[3 * p0 + 1];
    const float pz0 = points[3 * p0 + 2];
    const float px1 = points[3 * p1 + 0];
    const float py1 = points[3 * p1 + 1];
    const float pz1 = points[3 * p1 + 2];

    // Stage FT faces (threads 0..FT-1).
    if (tid < FT) {
        const int f  = fbase + tid;
        const int i0 = faces[3 * f + 0];
        const int i1 = faces[3 * f + 1];
        const int i2 = faces[3 * f + 2];
        const float ax = verts[3 * i0 + 0], ay = verts[3 * i0 + 1], az = verts[3 * i0 + 2];
        const float bx = verts[3 * i1 + 0], by = verts[3 * i1 + 1], bz = verts[3 * i1 + 2];
        const float cx = verts[3 * i2 + 0], cy = verts[3 * i2 + 1], cz = verts[3 * i2 + 2];
        stri[tid][0] = make_float4(ax, ay, az, bx);
        stri[tid][1] = make_float4(by, bz, cx, cy);
        stri[tid][2] = make_float4(cz, fs(bx, ax), fs(by, ay), fs(bz, az));
        stri[tid][3] = make_float4(fs(cx, ax), fs(cy, ay), fs(cz, az), 0.0f);
    }
    __syncthreads();

    float best0 = CUDART_INF_F, best1 = CUDART_INF_F;
    int   bestf0 = fbase,       bestf1 = fbase;

    #pragma unroll 8
    for (int i = 0; i < FT; ++i) {
        const float4 t0 = stri[i][0];
        const float4 t1 = stri[i][1];
        const float4 t2 = stri[i][2];
        const float4 t3 = stri[i][3];
        const float ax = t0.x, ay = t0.y, az = t0.z;
        const float bx = t0.w, by = t1.x, bz = t1.y;
        const float cx = t1.z, cy = t1.w, cz = t2.x;
        const float abx = t2.y, aby = t2.z, abz = t2.w;
        const float acx = t3.x, acy = t3.y, acz = t3.z;
        const int fidx = fbase + i;

        point_face(px0, py0, pz0, ax, ay, az, bx, by, bz, cx, cy, cz,
                   abx, aby, abz, acx, acy, acz, fidx, best0, bestf0);
        point_face(px1, py1, pz1, ax, ay, az, bx, by, bz, cx, cy, cz,
                   abx, aby, abz, acx, acy, acz, fidx, best1, bestf1);
    }

    // Inverted pack: max(~pk) == min(pk); ties -> lowest face index.
    const unsigned long long pk0 =
        ~(((unsigned long long)__float_as_uint(best0) << 32) | (unsigned int)bestf0);
    const unsigned long long pk1 =
        ~(((unsigned long long)__float_as_uint(best1) << 32) | (unsigned int)bestf1);
    atomicMax(&g_pack[p0], pk0);
    atomicMax(&g_pack[p1], pk1);
}

// Parallel unpack: 32 blocks x 256 threads, one point per thread.
// Writes dist/assoc, re-arms g_pack, and produces one deterministic
// per-block partial sum (fixed tree order).
__global__ __launch_bounds__(UNPACK_TPB)
void msdf_unpack_kernel(float* __restrict__ out) {
    __shared__ float ssum[UNPACK_TPB];
    const int tid = threadIdx.x;
    const int p   = blockIdx.x * UNPACK_TPB + tid;

    const unsigned long long pk = ~g_pack[p];   // un-invert
    g_pack[p] = 0ull;                           // re-arm for next launch
    const float d = __uint_as_float((unsigned int)(pk >> 32));
    const int idx = (int)(unsigned int)(pk & 0xFFFFFFFFull);
    out[1 + p]       = d;
    out[1 + P_N + p] = (float)idx;

    ssum[tid] = d;
    __syncthreads();
    #pragma unroll
    for (int s = UNPACK_TPB / 2; s > 0; s >>= 1) {
        if (tid < s) ssum[tid] += ssum[tid + s];
        __syncthreads();
    }
    if (tid == 0) g_partial[blockIdx.x] = ssum[0];
}

// Tiny deterministic loss: fixed ascending-order sum of the 32 partials.
__global__ void msdf_loss_kernel(float* __restrict__ out) {
    if (threadIdx.x == 0) {
        float acc = 0.0f;
        #pragma unroll
        for (int i = 0; i < UNPACK_BLOCKS; ++i) acc += g_partial[i];
        out[0] = acc * (1000.0f / (float)P_N);
    }
}

extern "C" void kernel_launch(void* const* d_in, const int* in_sizes, int n_in,
                              void* d_out, int out_size) {
    const float* verts  = (const float*)d_in[0];   // [V,3]
    const int*   faces  = (const int*)  d_in[1];   // [F,3]
    const float* points = (const float*)d_in[2];   // [P,3]
    float* out = (float*)d_out;                    // [1 + P + P] float32

    msdf_main_kernel<<<dim3(P_N / PPB, NSPLIT), TPB>>>(verts, faces, points);
    msdf_unpack_kernel<<<UNPACK_BLOCKS, UNPACK_TPB>>>(out);
    msdf_loss_kernel<<<1, 32>>>(out);
}

// round 15
// speedup vs baseline: 1.9516x; 1.0374x over previous
#include <cuda_runtime.h>
#include <cuda_bf16.h>
#include <math_constants.h>

// Problem constants (fixed by the reference: V=1024, F=2048, P=8192)
#define V_N 1024
#define F_N 2048
#define P_N 8192
#define EPSF 1e-12f

#define FT 32                  // faces per split (staged in SMEM)
#define NSPLIT (F_N / FT)      // 64
#define TPB 128                // threads per block
#define PPT 2                  // points per thread (explicit ILP)
#define PPB (TPB * PPT)        // 256 points per block

#define UNPACK_BLOCKS 32
#define UNPACK_TPB 256         // 32*256 = 8192 = one point per thread

// Cross-split argmin scratch, stored INVERTED so that:
//   - zero-init (module load / unpack reset) == "empty" (pk = all-ones)
//   - atomicMax(~pk) == atomicMin(pk): high bits = ~dist2_bits (monotonic),
//     low bits = ~face_idx (ties -> lowest face index wins == jnp.argmin)
// Unpack resets each slot to 0 after reading, so every graph replay sees
// a freshly initialized array. No init kernel needed.
__device__ unsigned long long g_pack[P_N];        // zero-initialized
__device__ float g_partial[UNPACK_BLOCKS];        // per-block loss partials

// ---- exact IEEE helpers (never contracted by ptxas) ----
__device__ __forceinline__ float fm(float a, float b) { return __fmul_rn(a, b); }
__device__ __forceinline__ float fa(float a, float b) { return __fadd_rn(a, b); }
__device__ __forceinline__ float fs(float a, float b) { return __fsub_rn(a, b); }
__device__ __forceinline__ float fd(float a, float b) { return __fdiv_rn(a, b); }
// dot3 with XLA reduce order: ((x0*y0 + x1*y1) + x2*y2), no fma
__device__ __forceinline__ float dot3(float x0, float x1, float x2,
                                      float y0, float y1, float y2) {
    return fa(fa(fm(x0, y0), fm(x1, y1)), fm(x2, y2));
}

// One point vs one triangle: bit-for-bit with the XLA reference.
// ab/ac are hoisted per-face (identical subtraction, done at stage time).
__device__ __forceinline__ void point_face(
    float px, float py, float pz,
    float ax, float ay, float az,
    float bx, float by, float bz,
    float cx, float cy, float cz,
    float abx, float aby, float abz,
    float acx, float acy, float acz,
    int fidx, float& best, int& bestf)
{
    const float apx = fs(px, ax), apy = fs(py, ay), apz = fs(pz, az);
    const float d1 = dot3(abx, aby, abz, apx, apy, apz);
    const float d2 = dot3(acx, acy, acz, apx, apy, apz);

    const float bpx = fs(px, bx), bpy = fs(py, by), bpz = fs(pz, bz);
    const float d3 = dot3(abx, aby, abz, bpx, bpy, bpz);
    const float d4 = dot3(acx, acy, acz, bpx, bpy, bpz);

    const float qx = fs(px, cx), qy = fs(py, cy), qz = fs(pz, cz);
    const float d5 = dot3(abx, aby, abz, qx, qy, qz);
    const float d6 = dot3(acx, acy, acz, qx, qy, qz);

    const float vc = fs(fm(d1, d4), fm(d3, d2));
    const float vb = fs(fm(d5, d2), fm(d1, d6));
    const float va = fs(fm(d3, d6), fm(d5, d4));

    const float nbc = fs(d4, d3);               // d4 - d3
    const float s56 = fs(d5, d6);               // d5 - d6
    const float denom = fmaxf(fa(fa(va, vb), vc), EPSF);
    const float dAB = fmaxf(fs(d1, d3), EPSF);
    const float dAC = fmaxf(fs(d2, d6), EPSF);
    const float dBC = fmaxf(fa(nbc, s56), EPSF);

    // raw region conditions (A, B, AB, C, AC, BC)
    const bool cA  = (d1 <= 0.0f) && (d2 <= 0.0f);
    const bool cB  = (d3 >= 0.0f) && (d4 <= d3);
    const bool cAB = (vc <= 0.0f) && (d1 >= 0.0f) && (d3 <= 0.0f);
    const bool cC  = (d6 >= 0.0f) && (d5 <= d6);
    const bool cAC = (vb <= 0.0f) && (d2 >= 0.0f) && (d6 <= 0.0f);
    const bool cBC = (va <= 0.0f) && (nbc >= 0.0f) && (s56 >= 0.0f);

    // exclusive first-match predicates via cumulative-OR priority chain
    const bool n0 = cA;
    const bool n1 = n0 | cB;
    const bool n2 = n1 | cAB;
    const bool n3 = n2 | cC;
    const bool n4 = n3 | cAC;
    const bool eB  = cB  && !n0;
    const bool eAB = cAB && !n1;
    const bool eC  = cC  && !n2;
    const bool eAC = cAC && !n3;
    const bool eBC = cBC && !n4;

    // Exactly TWO div.rn per pair, operands chosen so the SELECTED branch's
    // value is bit-identical to the reference's.
    const float numv = eAB ? d1  : eBC ? nbc : vb;
    const float denv = eAB ? dAB : eBC ? dBC : denom;
    const float numw = eAC ? d2  : eBC ? nbc : vc;
    const float denw = eAC ? dAC : eBC ? dBC : denom;

    const float qv = fd(numv, denv);
    const float qw = fd(numw, denw);

    // bv: A/C/AC -> 0, B -> 1, BC -> 1-t_bc, AB/interior -> qv
    float bv = eBC ? fs(1.0f, qv) : qv;
    bv = eB ? 1.0f : bv;
    bv = (cA | eC | eAC) ? 0.0f : bv;
    // bw: A/B/AB -> 0, C -> 1, AC/BC/interior -> qw
    float bw = eC ? 1.0f : qw;
    bw = (n1 | eAB) ? 0.0f : bw;   // n1|eAB == cA|eB|eAB (first-match A,B,AB)

    const float bu = fs(fs(1.0f, bv), bw);      // (1 - bv) - bw

    // cp = ((a*bu) + (b*bv)) + (c*bw), per component
    const float ox = fa(fa(fm(ax, bu), fm(bx, bv)), fm(cx, bw));
    const float oy = fa(fa(fm(ay, bu), fm(by, bv)), fm(cy, bw));
    const float oz = fa(fa(fm(az, bu), fm(bz, bv)), fm(cz, bw));

    // dist2 = ((dx^2 + dy^2) + dz^2)
    const float dx = fs(px, ox), dy = fs(py, oy), dz = fs(pz, oz);
    const float d2v = fa(fa(fm(dx, dx), fm(dy, dy)), fm(dz, dz));

    if (d2v < best) {   // strict < keeps earliest face on exact ties
        best  = d2v;
        bestf = fidx;
    }
}

__global__ __launch_bounds__(TPB, 8)
void msdf_main_kernel(const float* __restrict__ verts,
                      const int*   __restrict__ faces,
                      const float* __restrict__ points) {
    // float4-packed face stage, ab/ac precomputed at stage time:
    //   stri[i][0]=(ax,ay,az,bx)   stri[i][1]=(by,bz,cx,cy)
    //   stri[i][2]=(cz,abx,aby,abz) stri[i][3]=(acx,acy,acz,-)
    // Broadcast LDS.128, conflict-free.
    __shared__ float4 stri[FT][4];

    const int fbase = blockIdx.y * FT;
    const int tid = threadIdx.x;

    // Load this thread's two points first (overlaps with staging latency).
    const int p0 = blockIdx.x * PPB + tid;
    const int p1 = p0 + TPB;
    const float px0 = points[3 * p0 + 0];
    const float py0 = points[3 * p0 + 1];
    const float pz0 = points[3 * p0 + 2];
    const float px1 = points[3 * p1 + 0];
    const float py1 = points[3 * p1 + 1];
    const float pz1 = points[3 * p1 + 2];

    // Stage FT faces (threads 0..FT-1).
    if (tid < FT) {
        const int f  = fbase + tid;
        const int i0 = faces[3 * f + 0];
        const int i1 = faces[3 * f + 1];
        const int i2 = faces[3 * f + 2];
        const float ax = verts[3 * i0 + 0], ay = verts[3 * i0 + 1], az = verts[3 * i0 + 2];
        const float bx = verts[3 * i1 + 0], by = verts[3 * i1 + 1], bz = verts[3 * i1 + 2];
        const float cx = verts[3 * i2 + 0], cy = verts[3 * i2 + 1], cz = verts[3 * i2 + 2];
        stri[tid][0] = make_float4(ax, ay, az, bx);
        stri[tid][1] = make_float4(by, bz, cx, cy);
        stri[tid][2] = make_float4(cz, fs(bx, ax), fs(by, ay), fs(bz, az));
        stri[tid][3] = make_float4(fs(cx, ax), fs(cy, ay), fs(cz, az), 0.0f);
    }
    __syncthreads();

    float best0 = CUDART_INF_F, best1 = CUDART_INF_F;
    int   bestf0 = fbase,       bestf1 = fbase;

    #pragma unroll 8
    for (int i = 0; i < FT; ++i) {
        const float4 t0 = stri[i][0];
        const float4 t1 = stri[i][1];
        const float4 t2 = stri[i][2];
        const float4 t3 = stri[i][3];
        const float ax = t0.x, ay = t0.y, az = t0.z;
        const float bx = t0.w, by = t1.x, bz = t1.y;
        const float cx = t1.z, cy = t1.w, cz = t2.x;
        const float abx = t2.y, aby = t2.z, abz = t2.w;
        const float acx = t3.x, acy = t3.y, acz = t3.z;
        const int fidx = fbase + i;

        point_face(px0, py0, pz0, ax, ay, az, bx, by, bz, cx, cy, cz,
                   abx, aby, abz, acx, acy, acz, fidx, best0, bestf0);
        point_face(px1, py1, pz1, ax, ay, az, bx, by, bz, cx, cy, cz,
                   abx, aby, abz, acx, acy, acz, fidx, best1, bestf1);
    }

    // Inverted pack: max(~pk) == min(pk); ties -> lowest face index.
    const unsigned long long pk0 =
        ~(((unsigned long long)__float_as_uint(best0) << 32) | (unsigned int)bestf0);
    const unsigned long long pk1 =
        ~(((unsigned long long)__float_as_uint(best1) << 32) | (unsigned int)bestf1);
    atomicMax(&g_pack[p0], pk0);
    atomicMax(&g_pack[p1], pk1);
}

// Parallel unpack: 32 blocks x 256 threads, one point per thread.
// Writes dist/assoc, re-arms g_pack, and produces one deterministic
// per-block partial sum (fixed tree order).
__global__ __launch_bounds__(UNPACK_TPB)
void msdf_unpack_kernel(float* __restrict__ out) {
    __shared__ float ssum[UNPACK_TPB];
    const int tid = threadIdx.x;
    const int p   = blockIdx.x * UNPACK_TPB + tid;

    const unsigned long long pk = ~g_pack[p];   // un-invert
    g_pack[p] = 0ull;                           // re-arm for next launch
    const float d = __uint_as_float((unsigned int)(pk >> 32));
    const int idx = (int)(unsigned int)(pk & 0xFFFFFFFFull);
    out[1 + p]       = d;
    out[1 + P_N + p] = (float)idx;

    ssum[tid] = d;
    __syncthreads();
    #pragma unroll
    for (int s = UNPACK_TPB / 2; s > 0; s >>= 1) {
        if (tid < s) ssum[tid] += ssum[tid + s];
        __syncthreads();
    }
    if (tid == 0) g_partial[blockIdx.x] = ssum[0];
}

// Tiny deterministic loss: fixed ascending-order sum of the 32 partials.
__global__ void msdf_loss_kernel(float* __restrict__ out) {
    if (threadIdx.x == 0) {
        float acc = 0.0f;
        #pragma unroll
        for (int i = 0; i < UNPACK_BLOCKS; ++i) acc += g_partial[i];
        out[0] = acc * (1000.0f / (float)P_N);
    }
}

extern "C" void kernel_launch(void* const* d_in, const int* in_sizes, int n_in,
                              void* d_out, int out_size) {
    const float* verts  = (const float*)d_in[0];   // [V,3]
    const int*   faces  = (const int*)  d_in[1];   // [F,3]
    const float* points = (const float*)d_in[2];   // [P,3]
    float* out = (float*)d_out;                    // [1 + P + P] float32

    msdf_main_kernel<<<dim3(P_N / PPB, NSPLIT), TPB>>>(verts, faces, points);
    msdf_unpack_kernel<<<UNPACK_BLOCKS, UNPACK_TPB>>>(out);
    msdf_loss_kernel<<<1, 32>>>(out);
}

// round 17
// speedup vs baseline: 2.1573x; 1.1054x over previous
#include <cuda_runtime.h>
#include <cuda_bf16.h>
#include <math_constants.h>

// Problem constants (fixed by the reference: V=1024, F=2048, P=8192)
#define V_N 1024
#define F_N 2048
#define P_N 8192
#define EPSF 1e-12f

#define FT 32                  // faces per split (staged in SMEM)
#define NSPLIT (F_N / FT)      // 64
#define TPB 128                // threads per block
#define PPT 2                  // points per thread (packed f32x2 lanes)
#define PPB (TPB * PPT)        // 256 points per block

#define UNPACK_BLOCKS 32
#define UNPACK_TPB 256         // 32*256 = 8192 = one point per thread

typedef unsigned long long u64;

// Cross-split argmin scratch, stored INVERTED so that:
//   - zero-init (module load / unpack reset) == "empty" (pk = all-ones)
//   - atomicMax(~pk) == atomicMin(pk): high bits = ~dist2_bits (monotonic),
//     low bits = ~face_idx (ties -> lowest face index wins == jnp.argmin)
// Unpack resets each slot to 0 after reading, so every graph replay sees
// a freshly initialized array. No init kernel needed.
__device__ u64 g_pack[P_N];                       // zero-initialized
__device__ float g_partial[UNPACK_BLOCKS];        // per-block loss partials

// ---- packed f32x2 helpers, ALL expressed as explicit FMA so ptxas has
// nothing to contract. Each op performs exactly ONE rounding per lane and is
// bit-identical to the scalar __f{mul,add,sub}_rn path. ----
__device__ __forceinline__ u64 FMA2(u64 a, u64 b, u64 c) {
    u64 r; asm("fma.rn.f32x2 %0, %1, %2, %3;" : "=l"(r) : "l"(a), "l"(b), "l"(c));
    return r;
}
#define ONE2_C  0x3F8000003F800000ull
#define NEG12_C 0xBF800000BF800000ull
// a*b == fma(a, b, +0): RN(a*b) (zero-sign of exact-zero products is benign here)
__device__ __forceinline__ u64 MUL2(u64 a, u64 b) { return FMA2(a, b, 0ull); }
// a+b == fma(a, 1, b): exact multiply, single rounding == add.rn
__device__ __forceinline__ u64 ADD2(u64 a, u64 b) { return FMA2(a, ONE2_C, b); }
// a-b == fma(b, -1, a): exact multiply, single rounding == sub.rn
__device__ __forceinline__ u64 SUB2(u64 a, u64 b) { return FMA2(b, NEG12_C, a); }

__device__ __forceinline__ u64 PK2(float lo, float hi) {
    u64 r; asm("mov.b64 %0, {%1, %2};" : "=l"(r) : "f"(lo), "f"(hi)); return r;
}
__device__ __forceinline__ void UPK2(u64 v, float& lo, float& hi) {
    asm("mov.b64 {%0, %1}, %2;" : "=f"(lo), "=f"(hi) : "l"(v));
}
// packed dot3 with XLA reduce order: ((x0*y0 + x1*y1) + x2*y2), no fusion
__device__ __forceinline__ u64 DOT3_2(u64 x0, u64 x1, u64 x2,
                                      u64 y0, u64 y1, u64 y2) {
    return ADD2(ADD2(MUL2(x0, y0), MUL2(x1, y1)), MUL2(x2, y2));
}

// ---- exact scalar IEEE helpers ----
__device__ __forceinline__ float fs(float a, float b) { return __fsub_rn(a, b); }
__device__ __forceinline__ float fd(float a, float b) { return __fdiv_rn(a, b); }

// Scalar per-point tail: region selection + the two guarded divisions.
// Identical predicate chain / operand choices as the proven R14 kernel, so
// the selected bv/bw values are bit-identical to the XLA reference.
__device__ __forceinline__ void tail_bvbw(
    float d1, float d2, float d3, float d4, float d5, float d6,
    float va, float vb, float vc, float nbc, float s56,
    float sden, float dab_r, float dac_r, float dbc_r,
    float& bv, float& bw)
{
    const float denom = fmaxf(sden,  EPSF);
    const float dAB   = fmaxf(dab_r, EPSF);
    const float dAC   = fmaxf(dac_r, EPSF);
    const float dBC   = fmaxf(dbc_r, EPSF);

    // raw region conditions (A, B, AB, C, AC, BC)
    const bool cA  = (d1 <= 0.0f) && (d2 <= 0.0f);
    const bool cB  = (d3 >= 0.0f) && (d4 <= d3);
    const bool cAB = (vc <= 0.0f) && (d1 >= 0.0f) && (d3 <= 0.0f);
    const bool cC  = (d6 >= 0.0f) && (d5 <= d6);
    const bool cAC = (vb <= 0.0f) && (d2 >= 0.0f) && (d6 <= 0.0f);
    const bool cBC = (va <= 0.0f) && (nbc >= 0.0f) && (s56 >= 0.0f);

    // exclusive first-match predicates via cumulative-OR priority chain
    const bool n0 = cA;
    const bool n1 = n0 | cB;
    const bool n2 = n1 | cAB;
    const bool n3 = n2 | cC;
    const bool n4 = n3 | cAC;
    const bool eB  = cB  && !n0;
    const bool eAB = cAB && !n1;
    const bool eC  = cC  && !n2;
    const bool eAC = cAC && !n3;
    const bool eBC = cBC && !n4;

    // Exactly TWO div.rn per pair, operands chosen so the SELECTED branch's
    // value is bit-identical to the reference's.
    const float numv = eAB ? d1  : eBC ? nbc : vb;
    const float denv = eAB ? dAB : eBC ? dBC : denom;
    const float numw = eAC ? d2  : eBC ? nbc : vc;
    const float denw = eAC ? dAC : eBC ? dBC : denom;

    const float qv = fd(numv, denv);
    const float qw = fd(numw, denw);

    // bv: A/C/AC -> 0, B -> 1, BC -> 1-t_bc, AB/interior -> qv
    float v = eBC ? fs(1.0f, qv) : qv;
    v = eB ? 1.0f : v;
    v = (cA | eC | eAC) ? 0.0f : v;
    // bw: A/B/AB -> 0, C -> 1, AC/BC/interior -> qw
    float w = eC ? 1.0f : qw;
    w = (n1 | eAB) ? 0.0f : w;   // n1|eAB == cA|eB|eAB (first-match A,B,AB)

    bv = v; bw = w;
}

__global__ __launch_bounds__(TPB, 6)
void msdf_main_kernel(const float* __restrict__ verts,
                      const int*   __restrict__ faces,
                      const float* __restrict__ points) {
    // Face stage with every value DUPLICATED into an f32x2 pair so LDS.128
    // returns broadcast-packed operands directly (no pack MOVs).
    // Layout per face (16 float2 slots = 128B):
    //   [0]=ax [1]=ay [2]=az [3]=bx [4]=by [5]=bz [6]=cx [7]=cy [8]=cz
    //   [9]=abx [10]=aby [11]=abz [12]=acx [13]=acy [14]=acz [15]=pad
    __shared__ __align__(16) float2 sface[FT][16];

    const int fbase = blockIdx.y * FT;
    const int tid = threadIdx.x;

    // Load this thread's two points (packed lanes: lo=p0, hi=p1).
    const int p0 = blockIdx.x * PPB + tid;
    const int p1 = p0 + TPB;
    const u64 ppx = PK2(points[3 * p0 + 0], points[3 * p1 + 0]);
    const u64 ppy = PK2(points[3 * p0 + 1], points[3 * p1 + 1]);
    const u64 ppz = PK2(points[3 * p0 + 2], points[3 * p1 + 2]);

    // Stage FT faces (threads 0..FT-1), duplicating each scalar.
    if (tid < FT) {
        const int f  = fbase + tid;
        const int i0 = faces[3 * f + 0];
        const int i1 = faces[3 * f + 1];
        const int i2 = faces[3 * f + 2];
        const float ax = verts[3 * i0 + 0], ay = verts[3 * i0 + 1], az = verts[3 * i0 + 2];
        const float bx = verts[3 * i1 + 0], by = verts[3 * i1 + 1], bz = verts[3 * i1 + 2];
        const float cx = verts[3 * i2 + 0], cy = verts[3 * i2 + 1], cz = verts[3 * i2 + 2];
        float2* w = sface[tid];
        w[0]  = make_float2(ax, ax); w[1]  = make_float2(ay, ay); w[2]  = make_float2(az, az);
        w[3]  = make_float2(bx, bx); w[4]  = make_float2(by, by); w[5]  = make_float2(bz, bz);
        w[6]  = make_float2(cx, cx); w[7]  = make_float2(cy, cy); w[8]  = make_float2(cz, cz);
        w[9]  = make_float2(fs(bx, ax), fs(bx, ax));
        w[10] = make_float2(fs(by, ay), fs(by, ay));
        w[11] = make_float2(fs(bz, az), fs(bz, az));
        w[12] = make_float2(fs(cx, ax), fs(cx, ax));
        w[13] = make_float2(fs(cy, ay), fs(cy, ay));
        w[14] = make_float2(fs(cz, az), fs(cz, az));
        w[15] = make_float2(0.0f, 0.0f);
    }
    __syncthreads();

    float best0 = CUDART_INF_F, best1 = CUDART_INF_F;
    int   bestf0 = fbase,       bestf1 = fbase;

    #pragma unroll 2
    for (int i = 0; i < FT; ++i) {
        const ulonglong2* up = reinterpret_cast<const ulonglong2*>(sface[i]);
        const ulonglong2 q0 = up[0], q1 = up[1], q2 = up[2], q3 = up[3];
        const ulonglong2 q4 = up[4], q5 = up[5], q6 = up[6], q7 = up[7];
        const u64 ax2 = q0.x, ay2 = q0.y, az2 = q1.x;
        const u64 bx2 = q1.y, by2 = q2.x, bz2 = q2.y;
        const u64 cx2 = q3.x, cy2 = q3.y, cz2 = q4.x;
        const u64 abx2 = q4.y, aby2 = q5.x, abz2 = q5.y;
        const u64 acx2 = q6.x, acy2 = q6.y, acz2 = q7.x;
        const int fidx = fbase + i;

        // ---- packed phase 1: both points at once, bit-exact per lane ----
        const u64 apx = SUB2(ppx, ax2), apy = SUB2(ppy, ay2), apz = SUB2(ppz, az2);
        const u64 d1v = DOT3_2(abx2, aby2, abz2, apx, apy, apz);
        const u64 d2v = DOT3_2(acx2, acy2, acz2, apx, apy, apz);

        const u64 bpx = SUB2(ppx, bx2), bpy = SUB2(ppy, by2), bpz = SUB2(ppz, bz2);
        const u64 d3v = DOT3_2(abx2, aby2, abz2, bpx, bpy, bpz);
        const u64 d4v = DOT3_2(acx2, acy2, acz2, bpx, bpy, bpz);

        const u64 qxv = SUB2(ppx, cx2), qyv = SUB2(ppy, cy2), qzv = SUB2(ppz, cz2);
        const u64 d5v = DOT3_2(abx2, aby2, abz2, qxv, qyv, qzv);
        const u64 d6v = DOT3_2(acx2, acy2, acz2, qxv, qyv, qzv);

        const u64 vc2 = SUB2(MUL2(d1v, d4v), MUL2(d3v, d2v));
        const u64 vb2 = SUB2(MUL2(d5v, d2v), MUL2(d1v, d6v));
        const u64 va2 = SUB2(MUL2(d3v, d6v), MUL2(d5v, d4v));

        const u64 nbc2 = SUB2(d4v, d3v);
        const u64 s562 = SUB2(d5v, d6v);
        const u64 sden2 = ADD2(ADD2(va2, vb2), vc2);
        const u64 dab2 = SUB2(d1v, d3v);
        const u64 dac2 = SUB2(d2v, d6v);
        const u64 dbc2 = ADD2(nbc2, s562);

        // ---- scalar tails (predicates + divisions), one per lane ----
        float d1a, d1b, d2a, d2b, d3a, d3b, d4a, d4b, d5a, d5b, d6a, d6b;
        UPK2(d1v, d1a, d1b); UPK2(d2v, d2a, d2b); UPK2(d3v, d3a, d3b);
        UPK2(d4v, d4a, d4b); UPK2(d5v, d5a, d5b); UPK2(d6v, d6a, d6b);
        float vaa, vab, vba, vbb, vca, vcb;
        UPK2(va2, vaa, vab); UPK2(vb2, vba, vbb); UPK2(vc2, vca, vcb);
        float nbca, nbcb, s56a, s56b, sdena, sdenb, daba, dabb, daca, dacb, dbca, dbcb;
        UPK2(nbc2, nbca, nbcb); UPK2(s562, s56a, s56b); UPK2(sden2, sdena, sdenb);
        UPK2(dab2, daba, dabb); UPK2(dac2, daca, dacb); UPK2(dbc2, dbca, dbcb);

        float bv0, bw0, bv1, bw1;
        tail_bvbw(d1a, d2a, d3a, d4a, d5a, d6a, vaa, vba, vca,
                  nbca, s56a, sdena, daba, daca, dbca, bv0, bw0);
        tail_bvbw(d1b, d2b, d3b, d4b, d5b, d6b, vab, vbb, vcb,
                  nbcb, s56b, sdenb, dabb, dacb, dbcb, bv1, bw1);

        // ---- packed phase 2: closest point + dist2 ----
        const u64 bv2p = PK2(bv0, bv1);
        const u64 bw2p = PK2(bw0, bw1);
        const u64 bu2p = SUB2(SUB2(ONE2_C, bv2p), bw2p);   // (1 - bv) - bw

        const u64 ox2 = ADD2(ADD2(MUL2(ax2, bu2p), MUL2(bx2, bv2p)), MUL2(cx2, bw2p));
        const u64 oy2 = ADD2(ADD2(MUL2(ay2, bu2p), MUL2(by2, bv2p)), MUL2(cy2, bw2p));
        const u64 oz2 = ADD2(ADD2(MUL2(az2, bu2p), MUL2(bz2, bv2p)), MUL2(cz2, bw2p));

        const u64 dxp = SUB2(ppx, ox2), dyp = SUB2(ppy, oy2), dzp = SUB2(ppz, oz2);
        const u64 dd2 = ADD2(ADD2(MUL2(dxp, dxp), MUL2(dyp, dyp)), MUL2(dzp, dzp));

        float dd0, dd1;
        UPK2(dd2, dd0, dd1);
        if (dd0 < best0) { best0 = dd0; bestf0 = fidx; }  // strict <: earliest face on ties
        if (dd1 < best1) { best1 = dd1; bestf1 = fidx; }
    }

    // Inverted pack: max(~pk) == min(pk); ties -> lowest face index.
    const u64 pk0 =
        ~(((u64)__float_as_uint(best0) << 32) | (unsigned int)bestf0);
    const u64 pk1 =
        ~(((u64)__float_as_uint(best1) << 32) | (unsigned int)bestf1);
    atomicMax(&g_pack[p0], pk0);
    atomicMax(&g_pack[p1], pk1);
}

// Parallel unpack: 32 blocks x 256 threads, one point per thread.
// Writes dist/assoc, re-arms g_pack, and produces one deterministic
// per-block partial sum (fixed tree order).
__global__ __launch_bounds__(UNPACK_TPB)
void msdf_unpack_kernel(float* __restrict__ out) {
    __shared__ float ssum[UNPACK_TPB];
    const int tid = threadIdx.x;
    const int p   = blockIdx.x * UNPACK_TPB + tid;

    const u64 pk = ~g_pack[p];   // un-invert
    g_pack[p] = 0ull;            // re-arm for next launch
    const float d = __uint_as_float((unsigned int)(pk >> 32));
    const int idx = (int)(unsigned int)(pk & 0xFFFFFFFFull);
    out[1 + p]       = d;
    out[1 + P_N + p] = (float)idx;

    ssum[tid] = d;
    __syncthreads();
    #pragma unroll
    for (int s = UNPACK_TPB / 2; s > 0; s >>= 1) {
        if (tid < s) ssum[tid] += ssum[tid + s];
        __syncthreads();
    }
    if (tid == 0) g_partial[blockIdx.x] = ssum[0];
}

// Tiny deterministic loss: fixed ascending-order sum of the 32 partials.
__global__ void msdf_loss_kernel(float* __restrict__ out) {
    if (threadIdx.x == 0) {
        float acc = 0.0f;
        #pragma unroll
        for (int i = 0; i < UNPACK_BLOCKS; ++i) acc += g_partial[i];
        out[0] = acc * (1000.0f / (float)P_N);
    }
}

extern "C" void kernel_launch(void* const* d_in, const int* in_sizes, int n_in,
                              void* d_out, int out_size) {
    const float* verts  = (const float*)d_in[0];   // [V,3]
    const int*   faces  = (const int*)  d_in[1];   // [F,3]
    const float* points = (const float*)d_in[2];   // [P,3]
    float* out = (float*)d_out;                    // [1 + P + P] float32

    msdf_main_kernel<<<dim3(P_N / PPB, NSPLIT), TPB>>>(verts, faces, points);
    msdf_unpack_kernel<<<UNPACK_BLOCKS, UNPACK_TPB>>>(out);
    msdf_loss_kernel<<<1, 32>>>(out);
}